// round 6
// baseline (speedup 1.0000x reference)
#include <cuda_runtime.h>
#include <cuda_bf16.h>
#include <cstdint>

// Problem constants (fixed by the dataset)
#define DD   256          // hidden dim
#define BF   128          // B*F bases width
#define HBA  96           // H*B*A comb width
#define NCAT 224          // BF + HBA
#define GG   64           // graphs
#define EPSV 1e-5f

#define MAXN 50176
#define MAXE 851968
#define SCB  1024
#define MAXB ((MAXN + SCB - 1) / SCB)

// ---------------- device scratch (no allocations allowed) ----------------
__device__ float g_bases[MAXN * BF];
__device__ float g_comb [MAXN * HBA];
__device__ float g_h    [(size_t)MAXN * DD];
__device__ float g_Wcat [256 * NCAT];
__device__ int   g_cnt  [MAXN];
__device__ int   g_off  [MAXN + 1];
__device__ int   g_cur  [MAXN];
__device__ int   g_csr  [MAXE];
__device__ float g_dinv [MAXN];
__device__ float g_S1   [GG * DD];
__device__ float g_S2   [GG * DD];
__device__ float g_mu   [GG * DD];
__device__ float g_istd [GG * DD];
__device__ int   g_gstart[GG + 1];
__device__ int   g_bsum [MAXB];
__device__ int   g_boff [MAXB];

// ---------------- f32x2 packed helpers ----------------
__device__ __forceinline__ void ffma2(unsigned long long& d,
                                      unsigned long long a,
                                      unsigned long long b) {
    asm("fma.rn.f32x2 %0,%1,%2,%0;" : "+l"(d) : "l"(a), "l"(b));
}
__device__ __forceinline__ float2 unpack2(unsigned long long v) {
    float2 f;
    asm("mov.b64 {%0,%1},%2;" : "=f"(f.x), "=f"(f.y) : "l"(v));
    return f;
}

// ---------------- K0: init counters + stats ----------------
__global__ void k_init(int n) {
    int i = blockIdx.x * blockDim.x + threadIdx.x;
    if (i < n) g_cnt[i] = 0;
    if (i < GG * DD) { g_S1[i] = 0.f; g_S2[i] = 0.f; }
}

// ---------------- K1: concat weights ----------------
__global__ void k_wcat(const float* __restrict__ Wb, const float* __restrict__ Wc) {
    int i = blockIdx.x * blockDim.x + threadIdx.x;
    if (i >= 256 * NCAT) return;
    int k = i / NCAT, c = i % NCAT;
    g_Wcat[i] = (c < BF) ? Wb[k * BF + c] : Wc[k * HBA + (c - BF)];
}

// ---------------- K2: in-degree histogram over dst ----------------
__global__ void k_hist(const int* __restrict__ dst, int e) {
    int i = blockIdx.x * blockDim.x + threadIdx.x;
    if (i < e) atomicAdd(&g_cnt[dst[i]], 1);
}

// ---------------- K3a: per-block exclusive scan + dinv ----------------
__global__ __launch_bounds__(SCB) void k_scanA(int n) {
    __shared__ int warpsums[32];
    int t = threadIdx.x;
    int lane = t & 31, wrp = t >> 5;
    int i = blockIdx.x * SCB + t;
    int v = (i < n) ? g_cnt[i] : 0;
    int x = v;
    #pragma unroll
    for (int o = 1; o < 32; o <<= 1) {
        int y = __shfl_up_sync(0xFFFFFFFFu, x, o);
        if (lane >= o) x += y;
    }
    if (lane == 31) warpsums[wrp] = x;
    __syncthreads();
    if (t < 32) {
        int s = warpsums[t];
        #pragma unroll
        for (int o = 1; o < 32; o <<= 1) {
            int y = __shfl_up_sync(0xFFFFFFFFu, s, o);
            if (t >= o) s += y;
        }
        warpsums[t] = s;
    }
    __syncthreads();
    int incl = x + ((wrp > 0) ? warpsums[wrp - 1] : 0);
    if (i < n) {
        g_off[i] = incl - v;                    // block-local exclusive
        g_dinv[i] = rsqrtf((float)(v + 1));     // +1 self loop
    }
    if (t == SCB - 1) g_bsum[blockIdx.x] = incl;
}

// ---------------- K3b: 1-warp scan of block sums ----------------
__global__ void k_scanB(int nb, int etot, int n) {
    int lane = threadIdx.x;
    if (lane >= 32) return;
    int carry = 0;
    for (int base = 0; base < nb; base += 32) {
        int idx = base + lane;
        int v = (idx < nb) ? g_bsum[idx] : 0;
        int x = v;
        #pragma unroll
        for (int o = 1; o < 32; o <<= 1) {
            int y = __shfl_up_sync(0xFFFFFFFFu, x, o);
            if (lane >= o) x += y;
        }
        if (idx < nb) g_boff[idx] = carry + x - v;
        carry += __shfl_sync(0xFFFFFFFFu, x, 31);
    }
    if (lane == 0) g_off[n] = etot;
}

// ---------------- K3c: add block offsets ----------------
__global__ __launch_bounds__(SCB) void k_scanC(int n) {
    int i = blockIdx.x * SCB + threadIdx.x;
    if (i >= n) return;
    int e = g_off[i] + g_boff[blockIdx.x];
    g_off[i] = e;
    g_cur[i] = e;
}

// ---------------- K4: bucket-scatter edges into CSR ----------------
__global__ void k_scatter(const int* __restrict__ src, const int* __restrict__ dst, int e) {
    int i = blockIdx.x * blockDim.x + threadIdx.x;
    if (i >= e) return;
    int d = dst[i];
    int p = atomicAdd(&g_cur[d], 1);
    g_csr[p] = src[i];
}

// ---------------- K5: fused GEMM (bases + comb), f32x2 accumulators ----------------
#define GBM 128
#define GBN 64
#define GBK 16
__global__ __launch_bounds__(256) void k_gemm(const float* __restrict__ X,
                                              const float* __restrict__ bcomb, int M) {
    __shared__ float sA[GBK][GBM];
    __shared__ float sB2[GBK][GBN * 2];   // pre-splatted: each col value duplicated
    int tid = threadIdx.x;
    int row0 = blockIdx.x * GBM;
    int col0 = blockIdx.y * GBN;
    int ty = tid >> 4;  // 0..15 -> rows ty*8..+7
    int tx = tid & 15;  // cols tx*4..+3

    unsigned long long acc[4][4];
    #pragma unroll
    for (int p = 0; p < 4; p++)
        #pragma unroll
        for (int q = 0; q < 4; q++) acc[p][q] = 0ull;

    for (int k0 = 0; k0 < 256; k0 += GBK) {
        // load A 128x16 (transposed)
        #pragma unroll
        for (int it = 0; it < 2; it++) {
            int idx = tid + it * 256;     // 0..511
            int r = idx >> 2;
            int c4 = idx & 3;
            int grow = row0 + r;
            float4 v = make_float4(0.f, 0.f, 0.f, 0.f);
            if (grow < M) v = *(const float4*)(X + (size_t)grow * 256 + k0 + c4 * 4);
            sA[c4 * 4 + 0][r] = v.x;
            sA[c4 * 4 + 1][r] = v.y;
            sA[c4 * 4 + 2][r] = v.z;
            sA[c4 * 4 + 3][r] = v.w;
        }
        // load B 16x64 and pre-splat into f32x2 layout
        {
            int r = tid >> 4;
            int c4 = tid & 15;
            int gc = col0 + c4 * 4;
            float4 v = make_float4(0.f, 0.f, 0.f, 0.f);
            if (gc + 3 < NCAT) v = *(const float4*)(g_Wcat + (size_t)(k0 + r) * NCAT + gc);
            *(float4*)&sB2[r][c4 * 8]     = make_float4(v.x, v.x, v.y, v.y);
            *(float4*)&sB2[r][c4 * 8 + 4] = make_float4(v.z, v.z, v.w, v.w);
        }
        __syncthreads();
        #pragma unroll
        for (int k = 0; k < GBK; k++) {
            const unsigned long long* arow = (const unsigned long long*)&sA[k][ty * 8];
            unsigned long long ap0 = arow[0], ap1 = arow[1], ap2 = arow[2], ap3 = arow[3];
            const unsigned long long* brow = (const unsigned long long*)&sB2[k][tx * 8];
            unsigned long long bb0 = brow[0], bb1 = brow[1], bb2 = brow[2], bb3 = brow[3];
            ffma2(acc[0][0], ap0, bb0); ffma2(acc[0][1], ap0, bb1);
            ffma2(acc[0][2], ap0, bb2); ffma2(acc[0][3], ap0, bb3);
            ffma2(acc[1][0], ap1, bb0); ffma2(acc[1][1], ap1, bb1);
            ffma2(acc[1][2], ap1, bb2); ffma2(acc[1][3], ap1, bb3);
            ffma2(acc[2][0], ap2, bb0); ffma2(acc[2][1], ap2, bb1);
            ffma2(acc[2][2], ap2, bb2); ffma2(acc[2][3], ap2, bb3);
            ffma2(acc[3][0], ap3, bb0); ffma2(acc[3][1], ap3, bb1);
            ffma2(acc[3][2], ap3, bb2); ffma2(acc[3][3], ap3, bb3);
        }
        __syncthreads();
    }
    // store: vectorized STG.128 per row (4-col group never straddles the 128 boundary)
    int col = col0 + tx * 4;
    if (col >= NCAT) return;
    bool isBases = (col < BF);
    float4 bias4 = make_float4(0.f, 0.f, 0.f, 0.f);
    if (!isBases) bias4 = *(const float4*)(bcomb + (col - BF));
    #pragma unroll
    for (int p = 0; p < 4; p++) {
        float2 r0v = unpack2(acc[p][0]);
        float2 r1v = unpack2(acc[p][1]);
        float2 r2v = unpack2(acc[p][2]);
        float2 r3v = unpack2(acc[p][3]);
        int rbase = row0 + ty * 8 + p * 2;
        #pragma unroll
        for (int h = 0; h < 2; h++) {
            int rr = rbase + h;
            if (rr >= M) continue;
            float4 o;
            if (h == 0) o = make_float4(r0v.x, r1v.x, r2v.x, r3v.x);
            else        o = make_float4(r0v.y, r1v.y, r2v.y, r3v.y);
            if (isBases) {
                *(float4*)(g_bases + (size_t)rr * BF + col) = o;
            } else {
                o.x += bias4.x; o.y += bias4.y; o.z += bias4.z; o.w += bias4.w;
                *(float4*)(g_comb + (size_t)rr * HBA + (col - BF)) = o;
            }
        }
    }
}

// ---------------- K6: graph start offsets (batch is sorted) ----------------
__global__ void k_gstart(const int* __restrict__ batchv, int n) {
    int g = blockIdx.x * blockDim.x + threadIdx.x;
    if (g > GG) return;
    if (g == GG) { g_gstart[GG] = n; return; }
    int lo = 0, hi = n;
    while (lo < hi) {
        int mid = (lo + hi) >> 1;
        if (batchv[mid] < g) lo = mid + 1; else hi = mid;
    }
    g_gstart[g] = lo;
}

// ---------------- K7: warp-per-node aggregate + einsum + stats ----------------
#define AGG_WPB 8
__global__ __launch_bounds__(256) void k_agg(const float* __restrict__ conv_bias,
                                             const int* __restrict__ batchv, int n) {
    __shared__ float sAgg[AGG_WPB][3][128];
    __shared__ float sComb[AGG_WPB][96];
    __shared__ float sS1[DD], sS2[DD];
    __shared__ int sg0;
    int t = threadIdx.x;
    int w = t >> 5, lane = t & 31;
    int node0 = blockIdx.x * AGG_WPB;
    int node = node0 + w;
    if (t < DD) { sS1[t] = 0.f; sS2[t] = 0.f; }
    if (t == 0) sg0 = batchv[min(node0, n - 1)];
    __syncthreads();
    int g0 = sg0;

    if (node < n) {
        // prefetch comb early so it overlaps the edge loop
        sComb[w][lane]      = g_comb[(size_t)node * HBA + lane];
        sComb[w][lane + 32] = g_comb[(size_t)node * HBA + lane + 32];
        sComb[w][lane + 64] = g_comb[(size_t)node * HBA + lane + 64];

        const float4* bp = reinterpret_cast<const float4*>(g_bases);
        float di = g_dinv[node];
        float4 bv = bp[node * 32 + lane];
        float w2 = di * di;
        float4 asym = make_float4(bv.x * w2, bv.y * w2, bv.z * w2, bv.w * w2);
        float4 asum = bv;
        float4 amax = bv;
        int beg = g_off[node], end = g_off[node + 1];
        int j = beg;
        // unroll-by-4: 4 independent gather chains in flight (MLP 4-8)
        for (; j + 4 <= end; j += 4) {
            int s0 = __ldg(&g_csr[j]);
            int s1 = __ldg(&g_csr[j + 1]);
            int s2 = __ldg(&g_csr[j + 2]);
            int s3 = __ldg(&g_csr[j + 3]);
            float w0 = g_dinv[s0] * di;
            float w1 = g_dinv[s1] * di;
            float wS2 = g_dinv[s2] * di;
            float w3 = g_dinv[s3] * di;
            float4 m0 = bp[s0 * 32 + lane];
            float4 m1 = bp[s1 * 32 + lane];
            float4 m2 = bp[s2 * 32 + lane];
            float4 m3 = bp[s3 * 32 + lane];
            asym.x += m0.x * w0 + m1.x * w1 + m2.x * wS2 + m3.x * w3;
            asym.y += m0.y * w0 + m1.y * w1 + m2.y * wS2 + m3.y * w3;
            asym.z += m0.z * w0 + m1.z * w1 + m2.z * wS2 + m3.z * w3;
            asym.w += m0.w * w0 + m1.w * w1 + m2.w * wS2 + m3.w * w3;
            asum.x += m0.x + m1.x + m2.x + m3.x;
            asum.y += m0.y + m1.y + m2.y + m3.y;
            asum.z += m0.z + m1.z + m2.z + m3.z;
            asum.w += m0.w + m1.w + m2.w + m3.w;
            amax.x = fmaxf(fmaxf(fmaxf(amax.x, m0.x), fmaxf(m1.x, m2.x)), m3.x);
            amax.y = fmaxf(fmaxf(fmaxf(amax.y, m0.y), fmaxf(m1.y, m2.y)), m3.y);
            amax.z = fmaxf(fmaxf(fmaxf(amax.z, m0.z), fmaxf(m1.z, m2.z)), m3.z);
            amax.w = fmaxf(fmaxf(fmaxf(amax.w, m0.w), fmaxf(m1.w, m2.w)), m3.w);
        }
        for (; j < end; ++j) {
            int s = __ldg(&g_csr[j]);
            float ws = g_dinv[s] * di;
            float4 m = bp[s * 32 + lane];
            asym.x += m.x * ws; asym.y += m.y * ws; asym.z += m.z * ws; asym.w += m.w * ws;
            asum.x += m.x;      asum.y += m.y;      asum.z += m.z;      asum.w += m.w;
            amax.x = fmaxf(amax.x, m.x); amax.y = fmaxf(amax.y, m.y);
            amax.z = fmaxf(amax.z, m.z); amax.w = fmaxf(amax.w, m.w);
        }
        ((float4*)sAgg[w][0])[lane] = asym;
        ((float4*)sAgg[w][1])[lane] = asum;
        ((float4*)sAgg[w][2])[lane] = amax;
        __syncwarp();
        int g = batchv[node];
        bool local = (g == g0);
        #pragma unroll
        for (int jh = 0; jh < 8; jh++) {  // jh = head
            int tt = jh * 32 + lane;      // output channel
            float acc = conv_bias[tt];
            #pragma unroll
            for (int k = 0; k < 12; k++)  // k = a*B + b
                acc += sComb[w][jh * 12 + k] * sAgg[w][k >> 2][(k & 3) * 32 + lane];
            g_h[(size_t)node * DD + tt] = acc;
            float a2 = acc * acc;
            if (local) { atomicAdd(&sS1[tt], acc); atomicAdd(&sS2[tt], a2); }
            else { atomicAdd(&g_S1[g * DD + tt], acc); atomicAdd(&g_S2[g * DD + tt], a2); }
        }
    }
    __syncthreads();
    if (t < DD) {
        atomicAdd(&g_S1[g0 * DD + t], sS1[t]);
        atomicAdd(&g_S2[g0 * DD + t], sS2[t]);
    }
}

// ---------------- K8: finalize GraphNorm statistics ----------------
__global__ void k_fin(const float* __restrict__ alpha_v) {
    int i = blockIdx.x * blockDim.x + threadIdx.x;
    if (i >= GG * DD) return;
    int g = i / DD, d = i % DD;
    int cs = g_gstart[g + 1] - g_gstart[g];
    float c = fmaxf((float)cs, 1.f);
    float m = g_S1[i] / c;
    float a = alpha_v[d];
    float var = g_S2[i] / c - (2.f * a - a * a) * m * m;
    g_mu[i] = a * m;
    g_istd[i] = rsqrtf(var + EPSV);
}

// ---------------- K9: normalize + relu ----------------
__global__ void k_out(float* __restrict__ out, const int* __restrict__ batchv,
                      const float* __restrict__ gamma, const float* __restrict__ beta, int n) {
    int idx = blockIdx.x * blockDim.x + threadIdx.x;
    int total = n * (DD / 4);
    if (idx >= total) return;
    int node = idx >> 6;          // DD/4 = 64 float4 per row
    int c4 = idx & 63;
    int g = batchv[node];
    float4 hv = ((const float4*)g_h)[idx];
    int d = c4 * 4;
    float4 mu = *(const float4*)(g_mu + g * DD + d);
    float4 is = *(const float4*)(g_istd + g * DD + d);
    float4 ga = *(const float4*)(gamma + d);
    float4 be = *(const float4*)(beta + d);
    float4 r;
    r.x = fmaxf(0.f, ga.x * (hv.x - mu.x) * is.x + be.x);
    r.y = fmaxf(0.f, ga.y * (hv.y - mu.y) * is.y + be.y);
    r.z = fmaxf(0.f, ga.z * (hv.z - mu.z) * is.z + be.z);
    r.w = fmaxf(0.f, ga.w * (hv.w - mu.w) * is.w + be.w);
    ((float4*)out)[idx] = r;
}

// ---------------- launcher ----------------
extern "C" void kernel_launch(void* const* d_in, const int* in_sizes, int n_in,
                              void* d_out, int out_size) {
    const float* node      = (const float*)d_in[0];
    const float* Wb        = (const float*)d_in[2];
    const float* Wc        = (const float*)d_in[3];
    const float* bcomb     = (const float*)d_in[4];
    const float* conv_bias = (const float*)d_in[5];
    const float* gw        = (const float*)d_in[6];
    const float* gb        = (const float*)d_in[7];
    const float* gms       = (const float*)d_in[8];
    const int*   ei        = (const int*)d_in[9];
    const int*   batchv    = (const int*)d_in[10];
    int n = in_sizes[10];
    int e = in_sizes[9] / 2;
    const int* srcp = ei;
    const int* dstp = ei + e;
    float* out = (float*)d_out;

    int nb = (n + SCB - 1) / SCB;
    int initTot = (n > GG * DD) ? n : GG * DD;
    k_init<<<(initTot + 255) / 256, 256>>>(n);
    k_wcat<<<(256 * NCAT + 255) / 256, 256>>>(Wb, Wc);
    k_hist<<<(e + 255) / 256, 256>>>(dstp, e);
    k_scanA<<<nb, SCB>>>(n);
    k_scanB<<<1, 32>>>(nb, e, n);
    k_scanC<<<nb, SCB>>>(n);
    k_scatter<<<(e + 255) / 256, 256>>>(srcp, dstp, e);

    dim3 ggrid((n + GBM - 1) / GBM, (NCAT + GBN - 1) / GBN);
    k_gemm<<<ggrid, 256>>>(node, bcomb, n);

    k_gstart<<<1, 128>>>(batchv, n);
    k_agg<<<(n + AGG_WPB - 1) / AGG_WPB, 256>>>(conv_bias, batchv, n);
    k_fin<<<(GG * DD + 255) / 256, 256>>>(gms);
    k_out<<<(n * (DD / 4) + 255) / 256, 256>>>(out, batchv, gw, gb, n);
}

// round 8
// speedup vs baseline: 1.4200x; 1.4200x over previous
#include <cuda_runtime.h>
#include <cuda_bf16.h>
#include <cstdint>

// Problem constants (fixed by the dataset)
#define DD   256          // hidden dim
#define BF   128          // B*F bases width
#define HBA  96           // H*B*A comb width
#define NCAT 224          // BF + HBA
#define GG   64           // graphs
#define EPSV 1e-5f

#define MAXN 50176
#define MAXE 851968
#define SCB  1024
#define MAXB ((MAXN + SCB - 1) / SCB)

// ---------------- device scratch (no allocations allowed) ----------------
__device__ float g_bases[MAXN * BF];
__device__ float g_comb [MAXN * HBA];
__device__ float g_h    [(size_t)MAXN * DD];
__device__ float g_Wcat [256 * NCAT];
__device__ int   g_cnt  [MAXN];
__device__ int   g_off  [MAXN + 1];
__device__ int   g_cur  [MAXN];
__device__ int   g_csr  [MAXE];
__device__ float g_dinv [MAXN];
__device__ float g_S1   [GG * DD];
__device__ float g_S2   [GG * DD];
__device__ float g_mu   [GG * DD];
__device__ float g_istd [GG * DD];
__device__ int   g_gstart[GG + 1];
__device__ int   g_bsum [MAXB];
__device__ int   g_boff [MAXB];

// ---------------- f32x2 packed helpers ----------------
__device__ __forceinline__ unsigned long long pack2(float lo, float hi) {
    unsigned long long r;
    asm("mov.b64 %0,{%1,%2};" : "=l"(r) : "f"(lo), "f"(hi));
    return r;
}
__device__ __forceinline__ void ffma2(unsigned long long& d,
                                      unsigned long long a,
                                      unsigned long long b) {
    asm("fma.rn.f32x2 %0,%1,%2,%0;" : "+l"(d) : "l"(a), "l"(b));
}
__device__ __forceinline__ float2 unpack2(unsigned long long v) {
    float2 f;
    asm("mov.b64 {%0,%1},%2;" : "=f"(f.x), "=f"(f.y) : "l"(v));
    return f;
}

// ---------------- K0: init counters + stats ----------------
__global__ void k_init(int n) {
    int i = blockIdx.x * blockDim.x + threadIdx.x;
    if (i < n) g_cnt[i] = 0;
    if (i < GG * DD) { g_S1[i] = 0.f; g_S2[i] = 0.f; }
}

// ---------------- K1: concat weights ----------------
__global__ void k_wcat(const float* __restrict__ Wb, const float* __restrict__ Wc) {
    int i = blockIdx.x * blockDim.x + threadIdx.x;
    if (i >= 256 * NCAT) return;
    int k = i / NCAT, c = i % NCAT;
    g_Wcat[i] = (c < BF) ? Wb[k * BF + c] : Wc[k * HBA + (c - BF)];
}

// ---------------- K2: in-degree histogram over dst ----------------
__global__ void k_hist(const int* __restrict__ dst, int e) {
    int i = blockIdx.x * blockDim.x + threadIdx.x;
    if (i < e) atomicAdd(&g_cnt[dst[i]], 1);
}

// ---------------- K3a: per-block exclusive scan + dinv ----------------
__global__ __launch_bounds__(SCB) void k_scanA(int n) {
    __shared__ int warpsums[32];
    int t = threadIdx.x;
    int lane = t & 31, wrp = t >> 5;
    int i = blockIdx.x * SCB + t;
    int v = (i < n) ? g_cnt[i] : 0;
    int x = v;
    #pragma unroll
    for (int o = 1; o < 32; o <<= 1) {
        int y = __shfl_up_sync(0xFFFFFFFFu, x, o);
        if (lane >= o) x += y;
    }
    if (lane == 31) warpsums[wrp] = x;
    __syncthreads();
    if (t < 32) {
        int s = warpsums[t];
        #pragma unroll
        for (int o = 1; o < 32; o <<= 1) {
            int y = __shfl_up_sync(0xFFFFFFFFu, s, o);
            if (t >= o) s += y;
        }
        warpsums[t] = s;
    }
    __syncthreads();
    int incl = x + ((wrp > 0) ? warpsums[wrp - 1] : 0);
    if (i < n) {
        g_off[i] = incl - v;                    // block-local exclusive
        g_dinv[i] = rsqrtf((float)(v + 1));     // +1 self loop
    }
    if (t == SCB - 1) g_bsum[blockIdx.x] = incl;
}

// ---------------- K3b: 1-warp scan of block sums ----------------
__global__ void k_scanB(int nb, int etot, int n) {
    int lane = threadIdx.x;
    if (lane >= 32) return;
    int carry = 0;
    for (int base = 0; base < nb; base += 32) {
        int idx = base + lane;
        int v = (idx < nb) ? g_bsum[idx] : 0;
        int x = v;
        #pragma unroll
        for (int o = 1; o < 32; o <<= 1) {
            int y = __shfl_up_sync(0xFFFFFFFFu, x, o);
            if (lane >= o) x += y;
        }
        if (idx < nb) g_boff[idx] = carry + x - v;
        carry += __shfl_sync(0xFFFFFFFFu, x, 31);
    }
    if (lane == 0) g_off[n] = etot;
}

// ---------------- K3c: add block offsets ----------------
__global__ __launch_bounds__(SCB) void k_scanC(int n) {
    int i = blockIdx.x * SCB + threadIdx.x;
    if (i >= n) return;
    int e = g_off[i] + g_boff[blockIdx.x];
    g_off[i] = e;
    g_cur[i] = e;
}

// ---------------- K4: bucket-scatter edges into CSR ----------------
__global__ void k_scatter(const int* __restrict__ src, const int* __restrict__ dst, int e) {
    int i = blockIdx.x * blockDim.x + threadIdx.x;
    if (i >= e) return;
    int d = dst[i];
    int p = atomicAdd(&g_cur[d], 1);
    g_csr[p] = src[i];
}

// ---------------- K5: fused GEMM (bases + comb), f32x2 accumulators ----------------
// Inner loop: conflict-free LDS (A via LDS.64 broadcast, B via LDS.128) with
// register-side splat (pack2) — the SMEM pre-splat variant caused 4-way bank
// conflicts on the B loads and regressed the kernel.
#define GBM 128
#define GBN 64
#define GBK 16
__global__ __launch_bounds__(256) void k_gemm(const float* __restrict__ X,
                                              const float* __restrict__ bcomb, int M) {
    __shared__ float sA[GBK][GBM];
    __shared__ float sB[GBK][GBN];
    int tid = threadIdx.x;
    int row0 = blockIdx.x * GBM;
    int col0 = blockIdx.y * GBN;
    int ty = tid >> 4;  // 0..15 -> rows ty*8..+7
    int tx = tid & 15;  // cols tx*4..+3

    unsigned long long acc[4][4];
    #pragma unroll
    for (int p = 0; p < 4; p++)
        #pragma unroll
        for (int q = 0; q < 4; q++) acc[p][q] = 0ull;

    for (int k0 = 0; k0 < 256; k0 += GBK) {
        // load A 128x16 (transposed)
        #pragma unroll
        for (int it = 0; it < 2; it++) {
            int idx = tid + it * 256;     // 0..511
            int r = idx >> 2;
            int c4 = idx & 3;
            int grow = row0 + r;
            float4 v = make_float4(0.f, 0.f, 0.f, 0.f);
            if (grow < M) v = *(const float4*)(X + (size_t)grow * 256 + k0 + c4 * 4);
            sA[c4 * 4 + 0][r] = v.x;
            sA[c4 * 4 + 1][r] = v.y;
            sA[c4 * 4 + 2][r] = v.z;
            sA[c4 * 4 + 3][r] = v.w;
        }
        // load B 16x64
        {
            int r = tid >> 4;
            int c4 = tid & 15;
            int gc = col0 + c4 * 4;
            float4 v = make_float4(0.f, 0.f, 0.f, 0.f);
            if (gc + 3 < NCAT) v = *(const float4*)(g_Wcat + (size_t)(k0 + r) * NCAT + gc);
            *(float4*)&sB[r][c4 * 4] = v;
        }
        __syncthreads();
        #pragma unroll
        for (int k = 0; k < GBK; k++) {
            const unsigned long long* arow = (const unsigned long long*)&sA[k][ty * 8];
            unsigned long long ap0 = arow[0], ap1 = arow[1], ap2 = arow[2], ap3 = arow[3];
            float4 bq = *(const float4*)&sB[k][tx * 4];
            unsigned long long bb0 = pack2(bq.x, bq.x);
            unsigned long long bb1 = pack2(bq.y, bq.y);
            unsigned long long bb2 = pack2(bq.z, bq.z);
            unsigned long long bb3 = pack2(bq.w, bq.w);
            ffma2(acc[0][0], ap0, bb0); ffma2(acc[0][1], ap0, bb1);
            ffma2(acc[0][2], ap0, bb2); ffma2(acc[0][3], ap0, bb3);
            ffma2(acc[1][0], ap1, bb0); ffma2(acc[1][1], ap1, bb1);
            ffma2(acc[1][2], ap1, bb2); ffma2(acc[1][3], ap1, bb3);
            ffma2(acc[2][0], ap2, bb0); ffma2(acc[2][1], ap2, bb1);
            ffma2(acc[2][2], ap2, bb2); ffma2(acc[2][3], ap2, bb3);
            ffma2(acc[3][0], ap3, bb0); ffma2(acc[3][1], ap3, bb1);
            ffma2(acc[3][2], ap3, bb2); ffma2(acc[3][3], ap3, bb3);
        }
        __syncthreads();
    }
    // store: vectorized STG.128 per row (4-col group never straddles the 128 boundary)
    int col = col0 + tx * 4;
    if (col >= NCAT) return;
    bool isBases = (col < BF);
    float4 bias4 = make_float4(0.f, 0.f, 0.f, 0.f);
    if (!isBases) bias4 = *(const float4*)(bcomb + (col - BF));
    #pragma unroll
    for (int p = 0; p < 4; p++) {
        float2 r0v = unpack2(acc[p][0]);
        float2 r1v = unpack2(acc[p][1]);
        float2 r2v = unpack2(acc[p][2]);
        float2 r3v = unpack2(acc[p][3]);
        int rbase = row0 + ty * 8 + p * 2;
        #pragma unroll
        for (int h = 0; h < 2; h++) {
            int rr = rbase + h;
            if (rr >= M) continue;
            float4 o;
            if (h == 0) o = make_float4(r0v.x, r1v.x, r2v.x, r3v.x);
            else        o = make_float4(r0v.y, r1v.y, r2v.y, r3v.y);
            if (isBases) {
                *(float4*)(g_bases + (size_t)rr * BF + col) = o;
            } else {
                o.x += bias4.x; o.y += bias4.y; o.z += bias4.z; o.w += bias4.w;
                *(float4*)(g_comb + (size_t)rr * HBA + (col - BF)) = o;
            }
        }
    }
}

// ---------------- K6: graph start offsets (batch is sorted) ----------------
__global__ void k_gstart(const int* __restrict__ batchv, int n) {
    int g = blockIdx.x * blockDim.x + threadIdx.x;
    if (g > GG) return;
    if (g == GG) { g_gstart[GG] = n; return; }
    int lo = 0, hi = n;
    while (lo < hi) {
        int mid = (lo + hi) >> 1;
        if (batchv[mid] < g) lo = mid + 1; else hi = mid;
    }
    g_gstart[g] = lo;
}

// ---------------- K7: warp-per-node aggregate + einsum + stats ----------------
#define AGG_WPB 8
__global__ __launch_bounds__(256) void k_agg(const float* __restrict__ conv_bias,
                                             const int* __restrict__ batchv, int n) {
    __shared__ float sAgg[AGG_WPB][3][128];
    __shared__ float sComb[AGG_WPB][96];
    __shared__ float sS1[DD], sS2[DD];
    __shared__ int sg0;
    int t = threadIdx.x;
    int w = t >> 5, lane = t & 31;
    int node0 = blockIdx.x * AGG_WPB;
    int node = node0 + w;
    if (t < DD) { sS1[t] = 0.f; sS2[t] = 0.f; }
    if (t == 0) sg0 = batchv[min(node0, n - 1)];
    __syncthreads();
    int g0 = sg0;

    if (node < n) {
        // prefetch comb early so it overlaps the edge loop
        sComb[w][lane]      = g_comb[(size_t)node * HBA + lane];
        sComb[w][lane + 32] = g_comb[(size_t)node * HBA + lane + 32];
        sComb[w][lane + 64] = g_comb[(size_t)node * HBA + lane + 64];

        const float4* bp = reinterpret_cast<const float4*>(g_bases);
        float di = g_dinv[node];
        float4 bv = bp[node * 32 + lane];
        float w2 = di * di;
        float4 asym = make_float4(bv.x * w2, bv.y * w2, bv.z * w2, bv.w * w2);
        float4 asum = bv;
        float4 amax = bv;
        int beg = g_off[node], end = g_off[node + 1];
        int j = beg;
        // unroll-by-4: 4 independent gather chains in flight (MLP 4-8)
        for (; j + 4 <= end; j += 4) {
            int s0 = __ldg(&g_csr[j]);
            int s1 = __ldg(&g_csr[j + 1]);
            int s2 = __ldg(&g_csr[j + 2]);
            int s3 = __ldg(&g_csr[j + 3]);
            float w0 = g_dinv[s0] * di;
            float w1 = g_dinv[s1] * di;
            float wS2 = g_dinv[s2] * di;
            float w3 = g_dinv[s3] * di;
            float4 m0 = bp[s0 * 32 + lane];
            float4 m1 = bp[s1 * 32 + lane];
            float4 m2 = bp[s2 * 32 + lane];
            float4 m3 = bp[s3 * 32 + lane];
            asym.x += m0.x * w0 + m1.x * w1 + m2.x * wS2 + m3.x * w3;
            asym.y += m0.y * w0 + m1.y * w1 + m2.y * wS2 + m3.y * w3;
            asym.z += m0.z * w0 + m1.z * w1 + m2.z * wS2 + m3.z * w3;
            asym.w += m0.w * w0 + m1.w * w1 + m2.w * wS2 + m3.w * w3;
            asum.x += m0.x + m1.x + m2.x + m3.x;
            asum.y += m0.y + m1.y + m2.y + m3.y;
            asum.z += m0.z + m1.z + m2.z + m3.z;
            asum.w += m0.w + m1.w + m2.w + m3.w;
            amax.x = fmaxf(fmaxf(fmaxf(amax.x, m0.x), fmaxf(m1.x, m2.x)), m3.x);
            amax.y = fmaxf(fmaxf(fmaxf(amax.y, m0.y), fmaxf(m1.y, m2.y)), m3.y);
            amax.z = fmaxf(fmaxf(fmaxf(amax.z, m0.z), fmaxf(m1.z, m2.z)), m3.z);
            amax.w = fmaxf(fmaxf(fmaxf(amax.w, m0.w), fmaxf(m1.w, m2.w)), m3.w);
        }
        for (; j < end; ++j) {
            int s = __ldg(&g_csr[j]);
            float ws = g_dinv[s] * di;
            float4 m = bp[s * 32 + lane];
            asym.x += m.x * ws; asym.y += m.y * ws; asym.z += m.z * ws; asym.w += m.w * ws;
            asum.x += m.x;      asum.y += m.y;      asum.z += m.z;      asum.w += m.w;
            amax.x = fmaxf(amax.x, m.x); amax.y = fmaxf(amax.y, m.y);
            amax.z = fmaxf(amax.z, m.z); amax.w = fmaxf(amax.w, m.w);
        }
        ((float4*)sAgg[w][0])[lane] = asym;
        ((float4*)sAgg[w][1])[lane] = asum;
        ((float4*)sAgg[w][2])[lane] = amax;
        __syncwarp();
        int g = batchv[node];
        bool local = (g == g0);
        #pragma unroll
        for (int jh = 0; jh < 8; jh++) {  // jh = head
            int tt = jh * 32 + lane;      // output channel
            float acc = conv_bias[tt];
            #pragma unroll
            for (int k = 0; k < 12; k++)  // k = a*B + b
                acc += sComb[w][jh * 12 + k] * sAgg[w][k >> 2][(k & 3) * 32 + lane];
            g_h[(size_t)node * DD + tt] = acc;
            float a2 = acc * acc;
            if (local) { atomicAdd(&sS1[tt], acc); atomicAdd(&sS2[tt], a2); }
            else { atomicAdd(&g_S1[g * DD + tt], acc); atomicAdd(&g_S2[g * DD + tt], a2); }
        }
    }
    __syncthreads();
    if (t < DD) {
        atomicAdd(&g_S1[g0 * DD + t], sS1[t]);
        atomicAdd(&g_S2[g0 * DD + t], sS2[t]);
    }
}

// ---------------- K8: finalize GraphNorm statistics ----------------
__global__ void k_fin(const float* __restrict__ alpha_v) {
    int i = blockIdx.x * blockDim.x + threadIdx.x;
    if (i >= GG * DD) return;
    int g = i / DD, d = i % DD;
    int cs = g_gstart[g + 1] - g_gstart[g];
    float c = fmaxf((float)cs, 1.f);
    float m = g_S1[i] / c;
    float a = alpha_v[d];
    float var = g_S2[i] / c - (2.f * a - a * a) * m * m;
    g_mu[i] = a * m;
    g_istd[i] = rsqrtf(var + EPSV);
}

// ---------------- K9: normalize + relu ----------------
__global__ void k_out(float* __restrict__ out, const int* __restrict__ batchv,
                      const float* __restrict__ gamma, const float* __restrict__ beta, int n) {
    int idx = blockIdx.x * blockDim.x + threadIdx.x;
    int total = n * (DD / 4);
    if (idx >= total) return;
    int node = idx >> 6;          // DD/4 = 64 float4 per row
    int c4 = idx & 63;
    int g = batchv[node];
    float4 hv = ((const float4*)g_h)[idx];
    int d = c4 * 4;
    float4 mu = *(const float4*)(g_mu + g * DD + d);
    float4 is = *(const float4*)(g_istd + g * DD + d);
    float4 ga = *(const float4*)(gamma + d);
    float4 be = *(const float4*)(beta + d);
    float4 r;
    r.x = fmaxf(0.f, ga.x * (hv.x - mu.x) * is.x + be.x);
    r.y = fmaxf(0.f, ga.y * (hv.y - mu.y) * is.y + be.y);
    r.z = fmaxf(0.f, ga.z * (hv.z - mu.z) * is.z + be.z);
    r.w = fmaxf(0.f, ga.w * (hv.w - mu.w) * is.w + be.w);
    ((float4*)out)[idx] = r;
}

// ---------------- launcher ----------------
extern "C" void kernel_launch(void* const* d_in, const int* in_sizes, int n_in,
                              void* d_out, int out_size) {
    const float* node      = (const float*)d_in[0];
    const float* Wb        = (const float*)d_in[2];
    const float* Wc        = (const float*)d_in[3];
    const float* bcomb     = (const float*)d_in[4];
    const float* conv_bias = (const float*)d_in[5];
    const float* gw        = (const float*)d_in[6];
    const float* gb        = (const float*)d_in[7];
    const float* gms       = (const float*)d_in[8];
    const int*   ei        = (const int*)d_in[9];
    const int*   batchv    = (const int*)d_in[10];
    int n = in_sizes[10];
    int e = in_sizes[9] / 2;
    const int* srcp = ei;
    const int* dstp = ei + e;
    float* out = (float*)d_out;

    int nb = (n + SCB - 1) / SCB;
    int initTot = (n > GG * DD) ? n : GG * DD;
    k_init<<<(initTot + 255) / 256, 256>>>(n);
    k_wcat<<<(256 * NCAT + 255) / 256, 256>>>(Wb, Wc);
    k_hist<<<(e + 255) / 256, 256>>>(dstp, e);
    k_scanA<<<nb, SCB>>>(n);
    k_scanB<<<1, 32>>>(nb, e, n);
    k_scanC<<<nb, SCB>>>(n);
    k_scatter<<<(e + 255) / 256, 256>>>(srcp, dstp, e);

    dim3 ggrid((n + GBM - 1) / GBM, (NCAT + GBN - 1) / GBN);
    k_gemm<<<ggrid, 256>>>(node, bcomb, n);

    k_gstart<<<1, 128>>>(batchv, n);
    k_agg<<<(n + AGG_WPB - 1) / AGG_WPB, 256>>>(conv_bias, batchv, n);
    k_fin<<<(GG * DD + 255) / 256, 256>>>(gms);
    k_out<<<(n * (DD / 4) + 255) / 256, 256>>>(out, batchv, gw, gb, n);
}

// round 11
// speedup vs baseline: 1.9705x; 1.3876x over previous
#include <cuda_runtime.h>
#include <cuda_bf16.h>
#include <cstdint>

// Problem constants (fixed by the dataset)
#define DD   256          // hidden dim
#define BF   128          // B*F bases width
#define HBA  96           // H*B*A comb width
#define NCAT 224          // BF + HBA
#define GG   64           // graphs
#define EPSV 1e-5f

#define MAXN 50176
#define MAXE 851968
#define SCB  1024
#define MAXB ((MAXN + SCB - 1) / SCB)

#define NTILES (NCAT / 8)     // 28 n-tiles of 8 cols
#define KSTEPS (256 / 8)      // 32 k-steps of 8

// ---------------- device scratch (no allocations allowed) ----------------
__device__ float g_bases[MAXN * BF];
__device__ float g_comb [MAXN * HBA];
__device__ float g_h    [(size_t)MAXN * DD];
__device__ float g_Wfrag[NTILES * KSTEPS * 32 * 2];  // B in mma-fragment layout, tf32-rounded
__device__ int   g_cnt  [MAXN];
__device__ int   g_off  [MAXN + 1];
__device__ int   g_cur  [MAXN];
__device__ int   g_csr  [MAXE];
__device__ float g_dinv [MAXN];
__device__ float g_S1   [GG * DD];
__device__ float g_S2   [GG * DD];
__device__ float g_mu   [GG * DD];
__device__ float g_istd [GG * DD];
__device__ int   g_gstart[GG + 1];
__device__ int   g_bsum [MAXB];
__device__ int   g_boff [MAXB];

// ---------------- helpers ----------------
__device__ __forceinline__ float to_tf32(float x) {
    float r;
    asm("cvt.rna.tf32.f32 %0, %1;" : "=f"(r) : "f"(x));
    return r;
}
__device__ __forceinline__ uint32_t tf32_bits(float x) {
    float r;
    asm("cvt.rna.tf32.f32 %0, %1;" : "=f"(r) : "f"(x));
    return __float_as_uint(r);
}
// m16n8k8 tf32 mma (baseline sm_80+ PTX -> HMMA on sm_103, tensor pipe)
__device__ __forceinline__ void mma8(float* c, const uint32_t* a, uint32_t b0, uint32_t b1) {
    asm volatile(
        "mma.sync.aligned.m16n8k8.row.col.f32.tf32.tf32.f32 "
        "{%0,%1,%2,%3}, {%4,%5,%6,%7}, {%8,%9}, {%0,%1,%2,%3};"
        : "+f"(c[0]), "+f"(c[1]), "+f"(c[2]), "+f"(c[3])
        : "r"(a[0]), "r"(a[1]), "r"(a[2]), "r"(a[3]), "r"(b0), "r"(b1));
}

// ---------------- K0: init counters + stats ----------------
__global__ void k_init(int n) {
    int i = blockIdx.x * blockDim.x + threadIdx.x;
    if (i < n) g_cnt[i] = 0;
    if (i < GG * DD) { g_S1[i] = 0.f; g_S2[i] = 0.f; }
}

// ---------------- K1: build B in mma fragment layout (tf32-rounded) ----------------
// Fragment mapping (m16n8k8.row.col): b0 = B[k=tig][n=gid], b1 = B[k=tig+4][n=gid];
// linear layout: ((nt*KSTEPS + ks)*32 + lane)*2 + r  -> float2 per lane.
__global__ void k_wcat(const float* __restrict__ Wb, const float* __restrict__ Wc) {
    int i = blockIdx.x * blockDim.x + threadIdx.x;
    if (i >= NTILES * KSTEPS * 32 * 2) return;
    int r    = i & 1;
    int lane = (i >> 1) & 31;
    int ks   = (i >> 6) & 31;
    int nt   = i >> 11;
    int gid = lane >> 2, tig = lane & 3;
    int k = ks * 8 + tig + r * 4;
    int nn = nt * 8 + gid;
    float v = (nn < BF) ? Wb[k * BF + nn] : Wc[k * HBA + (nn - BF)];
    g_Wfrag[i] = to_tf32(v);
}

// ---------------- K2: in-degree histogram over dst ----------------
__global__ void k_hist(const int* __restrict__ dst, int e) {
    int i = blockIdx.x * blockDim.x + threadIdx.x;
    if (i < e) atomicAdd(&g_cnt[dst[i]], 1);
}

// ---------------- K3a: per-block exclusive scan + dinv ----------------
__global__ __launch_bounds__(SCB) void k_scanA(int n) {
    __shared__ int warpsums[32];
    int t = threadIdx.x;
    int lane = t & 31, wrp = t >> 5;
    int i = blockIdx.x * SCB + t;
    int v = (i < n) ? g_cnt[i] : 0;
    int x = v;
    #pragma unroll
    for (int o = 1; o < 32; o <<= 1) {
        int y = __shfl_up_sync(0xFFFFFFFFu, x, o);
        if (lane >= o) x += y;
    }
    if (lane == 31) warpsums[wrp] = x;
    __syncthreads();
    if (t < 32) {
        int s = warpsums[t];
        #pragma unroll
        for (int o = 1; o < 32; o <<= 1) {
            int y = __shfl_up_sync(0xFFFFFFFFu, s, o);
            if (t >= o) s += y;
        }
        warpsums[t] = s;
    }
    __syncthreads();
    int incl = x + ((wrp > 0) ? warpsums[wrp - 1] : 0);
    if (i < n) {
        g_off[i] = incl - v;                    // block-local exclusive
        g_dinv[i] = rsqrtf((float)(v + 1));     // +1 self loop
    }
    if (t == SCB - 1) g_bsum[blockIdx.x] = incl;
}

// ---------------- K3b: 1-warp scan of block sums ----------------
__global__ void k_scanB(int nb, int etot, int n) {
    int lane = threadIdx.x;
    if (lane >= 32) return;
    int carry = 0;
    for (int base = 0; base < nb; base += 32) {
        int idx = base + lane;
        int v = (idx < nb) ? g_bsum[idx] : 0;
        int x = v;
        #pragma unroll
        for (int o = 1; o < 32; o <<= 1) {
            int y = __shfl_up_sync(0xFFFFFFFFu, x, o);
            if (lane >= o) x += y;
        }
        if (idx < nb) g_boff[idx] = carry + x - v;
        carry += __shfl_sync(0xFFFFFFFFu, x, 31);
    }
    if (lane == 0) g_off[n] = etot;
}

// ---------------- K3c: add block offsets ----------------
__global__ __launch_bounds__(SCB) void k_scanC(int n) {
    int i = blockIdx.x * SCB + threadIdx.x;
    if (i >= n) return;
    int e = g_off[i] + g_boff[blockIdx.x];
    g_off[i] = e;
    g_cur[i] = e;
}

// ---------------- K4: bucket-scatter edges into CSR ----------------
__global__ void k_scatter(const int* __restrict__ src, const int* __restrict__ dst, int e) {
    int i = blockIdx.x * blockDim.x + threadIdx.x;
    if (i >= e) return;
    int d = dst[i];
    int p = atomicAdd(&g_cur[d], 1);
    g_csr[p] = src[i];
}

// ---------------- K5: tensor-core TF32 GEMM via mma.sync (fallback HMMA path) ----------------
// Block 128(M) x 112(N), grid.y = 2 covers NCAT=224. 8 warps as 4(M) x 2(N);
// warp tile 32 x 56 = 2 m-tiles x 7 n-tiles of m16n8k8. No SMEM: A coalesced
// from gmem (L1-cached, shared by the 2 N-warps), B from the fragment table.
#define TBM 128
#define TBN 112
__global__ __launch_bounds__(256) void k_gemm_mma(const float* __restrict__ X,
                                                  const float* __restrict__ bcomb, int M) {
    int tid = threadIdx.x;
    int wid = tid >> 5, lane = tid & 31;
    int warp_m = wid & 3;        // 0..3
    int warp_n = wid >> 2;       // 0..1
    int gid = lane >> 2, tig = lane & 3;

    int rowb = blockIdx.x * TBM + warp_m * 32;          // warp's M base
    int coln0 = blockIdx.y * TBN + warp_n * 56;         // warp's N base
    int ntg0 = coln0 >> 3;                              // global n-tile base (7 tiles)

    // clamped row pointers (invalid rows compute garbage, stores are guarded)
    const float* A0 = X + (size_t)min(rowb + gid,      M - 1) * 256;
    const float* A1 = X + (size_t)min(rowb + gid + 8,  M - 1) * 256;
    const float* A2 = X + (size_t)min(rowb + gid + 16, M - 1) * 256;
    const float* A3 = X + (size_t)min(rowb + gid + 24, M - 1) * 256;

    const float2* Bf = reinterpret_cast<const float2*>(g_Wfrag);

    float acc[2][7][4];
    #pragma unroll
    for (int mt = 0; mt < 2; mt++)
        #pragma unroll
        for (int nt = 0; nt < 7; nt++)
            #pragma unroll
            for (int q = 0; q < 4; q++) acc[mt][nt][q] = 0.f;

    #pragma unroll 4
    for (int ks = 0; ks < KSTEPS; ks++) {
        int k0 = ks * 8 + tig;
        uint32_t a0[4], a1[4];
        a0[0] = tf32_bits(__ldg(A0 + k0));
        a0[1] = tf32_bits(__ldg(A1 + k0));
        a0[2] = tf32_bits(__ldg(A0 + k0 + 4));
        a0[3] = tf32_bits(__ldg(A1 + k0 + 4));
        a1[0] = tf32_bits(__ldg(A2 + k0));
        a1[1] = tf32_bits(__ldg(A3 + k0));
        a1[2] = tf32_bits(__ldg(A2 + k0 + 4));
        a1[3] = tf32_bits(__ldg(A3 + k0 + 4));
        #pragma unroll
        for (int nt = 0; nt < 7; nt++) {
            float2 b2 = __ldg(&Bf[((size_t)(ntg0 + nt) * KSTEPS + ks) * 32 + lane]);
            uint32_t b0 = __float_as_uint(b2.x);
            uint32_t b1 = __float_as_uint(b2.y);
            mma8(acc[0][nt], a0, b0, b1);
            mma8(acc[1][nt], a1, b0, b1);
        }
    }

    // epilogue: d0,d1 -> row base+gid, cols col,col+1 ; d2,d3 -> row base+gid+8
    #pragma unroll
    for (int mt = 0; mt < 2; mt++) {
        int r1 = rowb + mt * 16 + gid;
        int r2 = r1 + 8;
        #pragma unroll
        for (int nt = 0; nt < 7; nt++) {
            int col = coln0 + nt * 8 + tig * 2;
            bool isB = (col < BF);
            float bx = 0.f, by = 0.f;
            if (!isB) { bx = bcomb[col - BF]; by = bcomb[col - BF + 1]; }
            if (r1 < M) {
                float2 v = make_float2(acc[mt][nt][0] + bx, acc[mt][nt][1] + by);
                if (isB) *(float2*)(g_bases + (size_t)r1 * BF + col) = v;
                else     *(float2*)(g_comb + (size_t)r1 * HBA + (col - BF)) = v;
            }
            if (r2 < M) {
                float2 v = make_float2(acc[mt][nt][2] + bx, acc[mt][nt][3] + by);
                if (isB) *(float2*)(g_bases + (size_t)r2 * BF + col) = v;
                else     *(float2*)(g_comb + (size_t)r2 * HBA + (col - BF)) = v;
            }
        }
    }
}

// ---------------- K6: graph start offsets (batch is sorted) ----------------
__global__ void k_gstart(const int* __restrict__ batchv, int n) {
    int g = blockIdx.x * blockDim.x + threadIdx.x;
    if (g > GG) return;
    if (g == GG) { g_gstart[GG] = n; return; }
    int lo = 0, hi = n;
    while (lo < hi) {
        int mid = (lo + hi) >> 1;
        if (batchv[mid] < g) lo = mid + 1; else hi = mid;
    }
    g_gstart[g] = lo;
}

// ---------------- K7: warp-per-node aggregate + einsum + stats ----------------
#define AGG_WPB 8
__global__ __launch_bounds__(256) void k_agg(const float* __restrict__ conv_bias,
                                             const int* __restrict__ batchv, int n) {
    __shared__ float sAgg[AGG_WPB][3][128];
    __shared__ float sComb[AGG_WPB][96];
    __shared__ float sS1[DD], sS2[DD];
    __shared__ int sg0;
    int t = threadIdx.x;
    int w = t >> 5, lane = t & 31;
    int node0 = blockIdx.x * AGG_WPB;
    int node = node0 + w;
    if (t < DD) { sS1[t] = 0.f; sS2[t] = 0.f; }
    if (t == 0) sg0 = batchv[min(node0, n - 1)];
    __syncthreads();
    int g0 = sg0;

    if (node < n) {
        // prefetch comb early so it overlaps the edge loop
        sComb[w][lane]      = g_comb[(size_t)node * HBA + lane];
        sComb[w][lane + 32] = g_comb[(size_t)node * HBA + lane + 32];
        sComb[w][lane + 64] = g_comb[(size_t)node * HBA + lane + 64];

        const float4* bp = reinterpret_cast<const float4*>(g_bases);
        float di = g_dinv[node];
        float4 bv = bp[node * 32 + lane];
        float w2 = di * di;
        float4 asym = make_float4(bv.x * w2, bv.y * w2, bv.z * w2, bv.w * w2);
        float4 asum = bv;
        float4 amax = bv;
        int beg = g_off[node], end = g_off[node + 1];
        int j = beg;
        // unroll-by-4: 4 independent gather chains in flight (MLP 4-8)
        for (; j + 4 <= end; j += 4) {
            int s0 = __ldg(&g_csr[j]);
            int s1 = __ldg(&g_csr[j + 1]);
            int s2 = __ldg(&g_csr[j + 2]);
            int s3 = __ldg(&g_csr[j + 3]);
            float w0 = g_dinv[s0] * di;
            float w1 = g_dinv[s1] * di;
            float wS2 = g_dinv[s2] * di;
            float w3 = g_dinv[s3] * di;
            float4 m0 = bp[s0 * 32 + lane];
            float4 m1 = bp[s1 * 32 + lane];
            float4 m2 = bp[s2 * 32 + lane];
            float4 m3 = bp[s3 * 32 + lane];
            asym.x += m0.x * w0 + m1.x * w1 + m2.x * wS2 + m3.x * w3;
            asym.y += m0.y * w0 + m1.y * w1 + m2.y * wS2 + m3.y * w3;
            asym.z += m0.z * w0 + m1.z * w1 + m2.z * wS2 + m3.z * w3;
            asym.w += m0.w * w0 + m1.w * w1 + m2.w * wS2 + m3.w * w3;
            asum.x += m0.x + m1.x + m2.x + m3.x;
            asum.y += m0.y + m1.y + m2.y + m3.y;
            asum.z += m0.z + m1.z + m2.z + m3.z;
            asum.w += m0.w + m1.w + m2.w + m3.w;
            amax.x = fmaxf(fmaxf(fmaxf(amax.x, m0.x), fmaxf(m1.x, m2.x)), m3.x);
            amax.y = fmaxf(fmaxf(fmaxf(amax.y, m0.y), fmaxf(m1.y, m2.y)), m3.y);
            amax.z = fmaxf(fmaxf(fmaxf(amax.z, m0.z), fmaxf(m1.z, m2.z)), m3.z);
            amax.w = fmaxf(fmaxf(fmaxf(amax.w, m0.w), fmaxf(m1.w, m2.w)), m3.w);
        }
        for (; j < end; ++j) {
            int s = __ldg(&g_csr[j]);
            float ws = g_dinv[s] * di;
            float4 m = bp[s * 32 + lane];
            asym.x += m.x * ws; asym.y += m.y * ws; asym.z += m.z * ws; asym.w += m.w * ws;
            asum.x += m.x;      asum.y += m.y;      asum.z += m.z;      asum.w += m.w;
            amax.x = fmaxf(amax.x, m.x); amax.y = fmaxf(amax.y, m.y);
            amax.z = fmaxf(amax.z, m.z); amax.w = fmaxf(amax.w, m.w);
        }
        ((float4*)sAgg[w][0])[lane] = asym;
        ((float4*)sAgg[w][1])[lane] = asum;
        ((float4*)sAgg[w][2])[lane] = amax;
        __syncwarp();
        int g = batchv[node];
        bool local = (g == g0);
        #pragma unroll
        for (int jh = 0; jh < 8; jh++) {  // jh = head
            int tt = jh * 32 + lane;      // output channel
            float acc = conv_bias[tt];
            #pragma unroll
            for (int k = 0; k < 12; k++)  // k = a*B + b
                acc += sComb[w][jh * 12 + k] * sAgg[w][k >> 2][(k & 3) * 32 + lane];
            g_h[(size_t)node * DD + tt] = acc;
            float a2 = acc * acc;
            if (local) { atomicAdd(&sS1[tt], acc); atomicAdd(&sS2[tt], a2); }
            else { atomicAdd(&g_S1[g * DD + tt], acc); atomicAdd(&g_S2[g * DD + tt], a2); }
        }
    }
    __syncthreads();
    if (t < DD) {
        atomicAdd(&g_S1[g0 * DD + t], sS1[t]);
        atomicAdd(&g_S2[g0 * DD + t], sS2[t]);
    }
}

// ---------------- K8: finalize GraphNorm statistics ----------------
__global__ void k_fin(const float* __restrict__ alpha_v) {
    int i = blockIdx.x * blockDim.x + threadIdx.x;
    if (i >= GG * DD) return;
    int g = i / DD, d = i % DD;
    int cs = g_gstart[g + 1] - g_gstart[g];
    float c = fmaxf((float)cs, 1.f);
    float m = g_S1[i] / c;
    float a = alpha_v[d];
    float var = g_S2[i] / c - (2.f * a - a * a) * m * m;
    g_mu[i] = a * m;
    g_istd[i] = rsqrtf(var + EPSV);
}

// ---------------- K9: normalize + relu ----------------
__global__ void k_out(float* __restrict__ out, const int* __restrict__ batchv,
                      const float* __restrict__ gamma, const float* __restrict__ beta, int n) {
    int idx = blockIdx.x * blockDim.x + threadIdx.x;
    int total = n * (DD / 4);
    if (idx >= total) return;
    int node = idx >> 6;          // DD/4 = 64 float4 per row
    int c4 = idx & 63;
    int g = batchv[node];
    float4 hv = ((const float4*)g_h)[idx];
    int d = c4 * 4;
    float4 mu = *(const float4*)(g_mu + g * DD + d);
    float4 is = *(const float4*)(g_istd + g * DD + d);
    float4 ga = *(const float4*)(gamma + d);
    float4 be = *(const float4*)(beta + d);
    float4 r;
    r.x = fmaxf(0.f, ga.x * (hv.x - mu.x) * is.x + be.x);
    r.y = fmaxf(0.f, ga.y * (hv.y - mu.y) * is.y + be.y);
    r.z = fmaxf(0.f, ga.z * (hv.z - mu.z) * is.z + be.z);
    r.w = fmaxf(0.f, ga.w * (hv.w - mu.w) * is.w + be.w);
    ((float4*)out)[idx] = r;
}

// ---------------- launcher ----------------
extern "C" void kernel_launch(void* const* d_in, const int* in_sizes, int n_in,
                              void* d_out, int out_size) {
    const float* node      = (const float*)d_in[0];
    const float* Wb        = (const float*)d_in[2];
    const float* Wc        = (const float*)d_in[3];
    const float* bcomb     = (const float*)d_in[4];
    const float* conv_bias = (const float*)d_in[5];
    const float* gw        = (const float*)d_in[6];
    const float* gb        = (const float*)d_in[7];
    const float* gms       = (const float*)d_in[8];
    const int*   ei        = (const int*)d_in[9];
    const int*   batchv    = (const int*)d_in[10];
    int n = in_sizes[10];
    int e = in_sizes[9] / 2;
    const int* srcp = ei;
    const int* dstp = ei + e;
    float* out = (float*)d_out;

    int nb = (n + SCB - 1) / SCB;
    int initTot = (n > GG * DD) ? n : GG * DD;
    k_init<<<(initTot + 255) / 256, 256>>>(n);
    k_wcat<<<(NTILES * KSTEPS * 32 * 2 + 255) / 256, 256>>>(Wb, Wc);
    k_hist<<<(e + 255) / 256, 256>>>(dstp, e);
    k_scanA<<<nb, SCB>>>(n);
    k_scanB<<<1, 32>>>(nb, e, n);
    k_scanC<<<nb, SCB>>>(n);
    k_scatter<<<(e + 255) / 256, 256>>>(srcp, dstp, e);

    dim3 ggrid((n + TBM - 1) / TBM, 2);
    k_gemm_mma<<<ggrid, 256>>>(node, bcomb, n);

    k_gstart<<<1, 128>>>(batchv, n);
    k_agg<<<(n + AGG_WPB - 1) / AGG_WPB, 256>>>(conv_bias, batchv, n);
    k_fin<<<(GG * DD + 255) / 256, 256>>>(gms);
    k_out<<<(n * (DD / 4) + 255) / 256, 256>>>(out, batchv, gw, gb, n);
}

// round 14
// speedup vs baseline: 2.0945x; 1.0630x over previous
#include <cuda_runtime.h>
#include <cuda_bf16.h>
#include <cstdint>

// Problem constants (fixed by the dataset)
#define DD   256          // hidden dim
#define BF   128          // B*F bases width
#define HBA  96           // H*B*A comb width
#define NCAT 224          // BF + HBA
#define GG   64           // graphs
#define EPSV 1e-5f

#define MAXN 50176
#define MAXE 851968
#define SCB  1024
#define MAXB ((MAXN + SCB - 1) / SCB)

#define NTILES (NCAT / 8)     // 28 n-tiles of 8 cols
#define KSTEPS (256 / 8)      // 32 k-steps of 8

// ---------------- device scratch (no allocations allowed) ----------------
__device__ float g_bases[MAXN * BF];
__device__ float g_comb [MAXN * HBA];
__device__ float g_h    [(size_t)MAXN * DD];
__device__ float g_Wfrag[NTILES * KSTEPS * 32 * 2];  // B in mma-fragment layout, tf32-rounded
__device__ int   g_cnt  [MAXN];
__device__ int   g_off  [MAXN + 1];
__device__ int   g_cur  [MAXN];
__device__ int2  g_edge [MAXE];     // packed {src, bits(dinv[src]*dinv[dst])}
__device__ float g_dinv [MAXN];
__device__ float g_S1   [GG * DD];
__device__ float g_S2   [GG * DD];
__device__ float g_mu   [GG * DD];
__device__ float g_istd [GG * DD];
__device__ int   g_gstart[GG + 1];
__device__ int   g_bsum [MAXB];
__device__ int   g_boff [MAXB];

// ---------------- helpers ----------------
__device__ __forceinline__ float to_tf32(float x) {
    float r;
    asm("cvt.rna.tf32.f32 %0, %1;" : "=f"(r) : "f"(x));
    return r;
}
__device__ __forceinline__ uint32_t tf32_bits(float x) {
    float r;
    asm("cvt.rna.tf32.f32 %0, %1;" : "=f"(r) : "f"(x));
    return __float_as_uint(r);
}
// m16n8k8 tf32 mma (baseline sm_80+ PTX -> HMMA on sm_103, tensor pipe)
__device__ __forceinline__ void mma8(float* c, const uint32_t* a, uint32_t b0, uint32_t b1) {
    asm volatile(
        "mma.sync.aligned.m16n8k8.row.col.f32.tf32.tf32.f32 "
        "{%0,%1,%2,%3}, {%4,%5,%6,%7}, {%8,%9}, {%0,%1,%2,%3};"
        : "+f"(c[0]), "+f"(c[1]), "+f"(c[2]), "+f"(c[3])
        : "r"(a[0]), "r"(a[1]), "r"(a[2]), "r"(a[3]), "r"(b0), "r"(b1));
}

// ---------------- K0: init counters + stats ----------------
__global__ void k_init(int n) {
    int i = blockIdx.x * blockDim.x + threadIdx.x;
    if (i < n) g_cnt[i] = 0;
    if (i < GG * DD) { g_S1[i] = 0.f; g_S2[i] = 0.f; }
}

// ---------------- K1: build B in mma fragment layout (tf32-rounded) ----------------
__global__ void k_wcat(const float* __restrict__ Wb, const float* __restrict__ Wc) {
    int i = blockIdx.x * blockDim.x + threadIdx.x;
    if (i >= NTILES * KSTEPS * 32 * 2) return;
    int r    = i & 1;
    int lane = (i >> 1) & 31;
    int ks   = (i >> 6) & 31;
    int nt   = i >> 11;
    int gid = lane >> 2, tig = lane & 3;
    int k = ks * 8 + tig + r * 4;
    int nn = nt * 8 + gid;
    float v = (nn < BF) ? Wb[k * BF + nn] : Wc[k * HBA + (nn - BF)];
    g_Wfrag[i] = to_tf32(v);
}

// ---------------- K2: in-degree histogram over dst ----------------
__global__ void k_hist(const int* __restrict__ dst, int e) {
    int i = blockIdx.x * blockDim.x + threadIdx.x;
    if (i < e) atomicAdd(&g_cnt[dst[i]], 1);
}

// ---------------- K3a: per-block exclusive scan + dinv ----------------
__global__ __launch_bounds__(SCB) void k_scanA(int n) {
    __shared__ int warpsums[32];
    int t = threadIdx.x;
    int lane = t & 31, wrp = t >> 5;
    int i = blockIdx.x * SCB + t;
    int v = (i < n) ? g_cnt[i] : 0;
    int x = v;
    #pragma unroll
    for (int o = 1; o < 32; o <<= 1) {
        int y = __shfl_up_sync(0xFFFFFFFFu, x, o);
        if (lane >= o) x += y;
    }
    if (lane == 31) warpsums[wrp] = x;
    __syncthreads();
    if (t < 32) {
        int s = warpsums[t];
        #pragma unroll
        for (int o = 1; o < 32; o <<= 1) {
            int y = __shfl_up_sync(0xFFFFFFFFu, s, o);
            if (t >= o) s += y;
        }
        warpsums[t] = s;
    }
    __syncthreads();
    int incl = x + ((wrp > 0) ? warpsums[wrp - 1] : 0);
    if (i < n) {
        g_off[i] = incl - v;                    // block-local exclusive
        g_dinv[i] = rsqrtf((float)(v + 1));     // +1 self loop
    }
    if (t == SCB - 1) g_bsum[blockIdx.x] = incl;
}

// ---------------- K3b: 1-warp scan of block sums ----------------
__global__ void k_scanB(int nb, int etot, int n) {
    int lane = threadIdx.x;
    if (lane >= 32) return;
    int carry = 0;
    for (int base = 0; base < nb; base += 32) {
        int idx = base + lane;
        int v = (idx < nb) ? g_bsum[idx] : 0;
        int x = v;
        #pragma unroll
        for (int o = 1; o < 32; o <<= 1) {
            int y = __shfl_up_sync(0xFFFFFFFFu, x, o);
            if (lane >= o) x += y;
        }
        if (idx < nb) g_boff[idx] = carry + x - v;
        carry += __shfl_sync(0xFFFFFFFFu, x, 31);
    }
    if (lane == 0) g_off[n] = etot;
}

// ---------------- K3c: add block offsets ----------------
__global__ __launch_bounds__(SCB) void k_scanC(int n) {
    int i = blockIdx.x * SCB + threadIdx.x;
    if (i >= n) return;
    int e = g_off[i] + g_boff[blockIdx.x];
    g_off[i] = e;
    g_cur[i] = e;
}

// ---------------- K4: scatter packed edge records {src, symweight} ----------------
__global__ void k_scatter(const int* __restrict__ src, const int* __restrict__ dst, int e) {
    int i = blockIdx.x * blockDim.x + threadIdx.x;
    if (i >= e) return;
    int d = dst[i];
    int s = src[i];
    int p = atomicAdd(&g_cur[d], 1);
    float w = g_dinv[s] * g_dinv[d];
    g_edge[p] = make_int2(s, __float_as_int(w));
}

// ---------------- K5: tensor-core TF32 GEMM via mma.sync (fallback HMMA path) ----------------
#define TBM 128
#define TBN 112
__global__ __launch_bounds__(256) void k_gemm_mma(const float* __restrict__ X,
                                                  const float* __restrict__ bcomb, int M) {
    int tid = threadIdx.x;
    int wid = tid >> 5, lane = tid & 31;
    int warp_m = wid & 3;        // 0..3
    int warp_n = wid >> 2;       // 0..1
    int gid = lane >> 2, tig = lane & 3;

    int rowb = blockIdx.x * TBM + warp_m * 32;          // warp's M base
    int coln0 = blockIdx.y * TBN + warp_n * 56;         // warp's N base
    int ntg0 = coln0 >> 3;                              // global n-tile base (7 tiles)

    // clamped row pointers (invalid rows compute garbage, stores are guarded)
    const float* A0 = X + (size_t)min(rowb + gid,      M - 1) * 256;
    const float* A1 = X + (size_t)min(rowb + gid + 8,  M - 1) * 256;
    const float* A2 = X + (size_t)min(rowb + gid + 16, M - 1) * 256;
    const float* A3 = X + (size_t)min(rowb + gid + 24, M - 1) * 256;

    const float2* Bf = reinterpret_cast<const float2*>(g_Wfrag);

    float acc[2][7][4];
    #pragma unroll
    for (int mt = 0; mt < 2; mt++)
        #pragma unroll
        for (int nt = 0; nt < 7; nt++)
            #pragma unroll
            for (int q = 0; q < 4; q++) acc[mt][nt][q] = 0.f;

    #pragma unroll 4
    for (int ks = 0; ks < KSTEPS; ks++) {
        int k0 = ks * 8 + tig;
        uint32_t a0[4], a1[4];
        a0[0] = tf32_bits(__ldg(A0 + k0));
        a0[1] = tf32_bits(__ldg(A1 + k0));
        a0[2] = tf32_bits(__ldg(A0 + k0 + 4));
        a0[3] = tf32_bits(__ldg(A1 + k0 + 4));
        a1[0] = tf32_bits(__ldg(A2 + k0));
        a1[1] = tf32_bits(__ldg(A3 + k0));
        a1[2] = tf32_bits(__ldg(A2 + k0 + 4));
        a1[3] = tf32_bits(__ldg(A3 + k0 + 4));
        #pragma unroll
        for (int nt = 0; nt < 7; nt++) {
            float2 b2 = __ldg(&Bf[((size_t)(ntg0 + nt) * KSTEPS + ks) * 32 + lane]);
            uint32_t b0 = __float_as_uint(b2.x);
            uint32_t b1 = __float_as_uint(b2.y);
            mma8(acc[0][nt], a0, b0, b1);
            mma8(acc[1][nt], a1, b0, b1);
        }
    }

    // epilogue: d0,d1 -> row base+gid, cols col,col+1 ; d2,d3 -> row base+gid+8
    #pragma unroll
    for (int mt = 0; mt < 2; mt++) {
        int r1 = rowb + mt * 16 + gid;
        int r2 = r1 + 8;
        #pragma unroll
        for (int nt = 0; nt < 7; nt++) {
            int col = coln0 + nt * 8 + tig * 2;
            bool isB = (col < BF);
            float bx = 0.f, by = 0.f;
            if (!isB) { bx = bcomb[col - BF]; by = bcomb[col - BF + 1]; }
            if (r1 < M) {
                float2 v = make_float2(acc[mt][nt][0] + bx, acc[mt][nt][1] + by);
                if (isB) *(float2*)(g_bases + (size_t)r1 * BF + col) = v;
                else     *(float2*)(g_comb + (size_t)r1 * HBA + (col - BF)) = v;
            }
            if (r2 < M) {
                float2 v = make_float2(acc[mt][nt][2] + bx, acc[mt][nt][3] + by);
                if (isB) *(float2*)(g_bases + (size_t)r2 * BF + col) = v;
                else     *(float2*)(g_comb + (size_t)r2 * HBA + (col - BF)) = v;
            }
        }
    }
}

// ---------------- K6: graph start offsets (batch is sorted) ----------------
__global__ void k_gstart(const int* __restrict__ batchv, int n) {
    int g = blockIdx.x * blockDim.x + threadIdx.x;
    if (g > GG) return;
    if (g == GG) { g_gstart[GG] = n; return; }
    int lo = 0, hi = n;
    while (lo < hi) {
        int mid = (lo + hi) >> 1;
        if (batchv[mid] < g) lo = mid + 1; else hi = mid;
    }
    g_gstart[g] = lo;
}

// ---------------- K7: warp-per-node aggregate + einsum + stats ----------------
#define AGG_WPB 8
__global__ __launch_bounds__(256) void k_agg(const float* __restrict__ conv_bias,
                                             const int* __restrict__ batchv, int n) {
    __shared__ float sAgg[AGG_WPB][3][128];
    __shared__ float sComb[AGG_WPB][96];
    __shared__ float sH [AGG_WPB][DD];   // per-warp h values for stats reduction
    __shared__ float sH2[AGG_WPB][DD];
    __shared__ int sg0;
    int t = threadIdx.x;
    int w = t >> 5, lane = t & 31;
    int node0 = blockIdx.x * AGG_WPB;
    int node = node0 + w;
    if (t == 0) sg0 = batchv[min(node0, n - 1)];
    __syncthreads();
    int g0 = sg0;

    if (node < n) {
        // prefetch comb early so it overlaps the edge loop
        sComb[w][lane]      = g_comb[(size_t)node * HBA + lane];
        sComb[w][lane + 32] = g_comb[(size_t)node * HBA + lane + 32];
        sComb[w][lane + 64] = g_comb[(size_t)node * HBA + lane + 64];

        const float4* bp = reinterpret_cast<const float4*>(g_bases);
        const int2* ep = g_edge;
        float di = g_dinv[node];
        float4 bv = bp[node * 32 + lane];
        float w2 = di * di;
        float4 asym = make_float4(bv.x * w2, bv.y * w2, bv.z * w2, bv.w * w2);
        float4 asum = bv;
        float4 amax = bv;
        int beg = g_off[node], end = g_off[node + 1];
        int j = beg;
        // unroll-by-4; packed edge records remove the dinv gather from the chain
        for (; j + 4 <= end; j += 4) {
            int2 e0 = __ldg(&ep[j]);
            int2 e1 = __ldg(&ep[j + 1]);
            int2 e2 = __ldg(&ep[j + 2]);
            int2 e3 = __ldg(&ep[j + 3]);
            float w0 = __int_as_float(e0.y);
            float w1 = __int_as_float(e1.y);
            float wS2 = __int_as_float(e2.y);
            float w3 = __int_as_float(e3.y);
            float4 m0 = bp[e0.x * 32 + lane];
            float4 m1 = bp[e1.x * 32 + lane];
            float4 m2 = bp[e2.x * 32 + lane];
            float4 m3 = bp[e3.x * 32 + lane];
            asym.x += m0.x * w0 + m1.x * w1 + m2.x * wS2 + m3.x * w3;
            asym.y += m0.y * w0 + m1.y * w1 + m2.y * wS2 + m3.y * w3;
            asym.z += m0.z * w0 + m1.z * w1 + m2.z * wS2 + m3.z * w3;
            asym.w += m0.w * w0 + m1.w * w1 + m2.w * wS2 + m3.w * w3;
            asum.x += m0.x + m1.x + m2.x + m3.x;
            asum.y += m0.y + m1.y + m2.y + m3.y;
            asum.z += m0.z + m1.z + m2.z + m3.z;
            asum.w += m0.w + m1.w + m2.w + m3.w;
            amax.x = fmaxf(fmaxf(fmaxf(amax.x, m0.x), fmaxf(m1.x, m2.x)), m3.x);
            amax.y = fmaxf(fmaxf(fmaxf(amax.y, m0.y), fmaxf(m1.y, m2.y)), m3.y);
            amax.z = fmaxf(fmaxf(fmaxf(amax.z, m0.z), fmaxf(m1.z, m2.z)), m3.z);
            amax.w = fmaxf(fmaxf(fmaxf(amax.w, m0.w), fmaxf(m1.w, m2.w)), m3.w);
        }
        for (; j < end; ++j) {
            int2 e0 = __ldg(&ep[j]);
            float ws = __int_as_float(e0.y);
            float4 m = bp[e0.x * 32 + lane];
            asym.x += m.x * ws; asym.y += m.y * ws; asym.z += m.z * ws; asym.w += m.w * ws;
            asum.x += m.x;      asum.y += m.y;      asum.z += m.z;      asum.w += m.w;
            amax.x = fmaxf(amax.x, m.x); amax.y = fmaxf(amax.y, m.y);
            amax.z = fmaxf(amax.z, m.z); amax.w = fmaxf(amax.w, m.w);
        }
        ((float4*)sAgg[w][0])[lane] = asym;
        ((float4*)sAgg[w][1])[lane] = asum;
        ((float4*)sAgg[w][2])[lane] = amax;
        __syncwarp();
        int g = batchv[node];
        bool local = (g == g0);
        #pragma unroll
        for (int jh = 0; jh < 8; jh++) {  // jh = head
            int tt = jh * 32 + lane;      // output channel
            float acc = conv_bias[tt];
            #pragma unroll
            for (int k = 0; k < 12; k++)  // k = a*B + b
                acc += sComb[w][jh * 12 + k] * sAgg[w][k >> 2][(k & 3) * 32 + lane];
            g_h[(size_t)node * DD + tt] = acc;
            float a2 = acc * acc;
            if (local) {
                sH[w][tt] = acc;
                sH2[w][tt] = a2;
            } else {
                sH[w][tt] = 0.f;
                sH2[w][tt] = 0.f;
                atomicAdd(&g_S1[g * DD + tt], acc);
                atomicAdd(&g_S2[g * DD + tt], a2);
            }
        }
    } else {
        // inactive warp: zero its reduction rows
        #pragma unroll
        for (int jh = 0; jh < 8; jh++) {
            int tt = jh * 32 + lane;
            sH[w][tt] = 0.f;
            sH2[w][tt] = 0.f;
        }
    }
    __syncthreads();
    if (t < DD) {
        float s1 = 0.f, s2 = 0.f;
        #pragma unroll
        for (int ww = 0; ww < AGG_WPB; ww++) { s1 += sH[ww][t]; s2 += sH2[ww][t]; }
        atomicAdd(&g_S1[g0 * DD + t], s1);
        atomicAdd(&g_S2[g0 * DD + t], s2);
    }
}

// ---------------- K8: finalize GraphNorm statistics ----------------
__global__ void k_fin(const float* __restrict__ alpha_v) {
    int i = blockIdx.x * blockDim.x + threadIdx.x;
    if (i >= GG * DD) return;
    int g = i / DD, d = i % DD;
    int cs = g_gstart[g + 1] - g_gstart[g];
    float c = fmaxf((float)cs, 1.f);
    float m = g_S1[i] / c;
    float a = alpha_v[d];
    float var = g_S2[i] / c - (2.f * a - a * a) * m * m;
    g_mu[i] = a * m;
    g_istd[i] = rsqrtf(var + EPSV);
}

// ---------------- K9: normalize + relu ----------------
__global__ void k_out(float* __restrict__ out, const int* __restrict__ batchv,
                      const float* __restrict__ gamma, const float* __restrict__ beta, int n) {
    int idx = blockIdx.x * blockDim.x + threadIdx.x;
    int total = n * (DD / 4);
    if (idx >= total) return;
    int node = idx >> 6;          // DD/4 = 64 float4 per row
    int c4 = idx & 63;
    int g = __ldg(&batchv[node]);
    float4 hv = ((const float4*)g_h)[idx];
    int d = c4 * 4;
    float4 mu = *(const float4*)(g_mu + g * DD + d);
    float4 is = *(const float4*)(g_istd + g * DD + d);
    float4 ga = *(const float4*)(gamma + d);
    float4 be = *(const float4*)(beta + d);
    float4 r;
    r.x = fmaxf(0.f, ga.x * (hv.x - mu.x) * is.x + be.x);
    r.y = fmaxf(0.f, ga.y * (hv.y - mu.y) * is.y + be.y);
    r.z = fmaxf(0.f, ga.z * (hv.z - mu.z) * is.z + be.z);
    r.w = fmaxf(0.f, ga.w * (hv.w - mu.w) * is.w + be.w);
    ((float4*)out)[idx] = r;
}

// ---------------- launcher ----------------
extern "C" void kernel_launch(void* const* d_in, const int* in_sizes, int n_in,
                              void* d_out, int out_size) {
    const float* node      = (const float*)d_in[0];
    const float* Wb        = (const float*)d_in[2];
    const float* Wc        = (const float*)d_in[3];
    const float* bcomb     = (const float*)d_in[4];
    const float* conv_bias = (const float*)d_in[5];
    const float* gw        = (const float*)d_in[6];
    const float* gb        = (const float*)d_in[7];
    const float* gms       = (const float*)d_in[8];
    const int*   ei        = (const int*)d_in[9];
    const int*   batchv    = (const int*)d_in[10];
    int n = in_sizes[10];
    int e = in_sizes[9] / 2;
    const int* srcp = ei;
    const int* dstp = ei + e;
    float* out = (float*)d_out;

    int nb = (n + SCB - 1) / SCB;
    int initTot = (n > GG * DD) ? n : GG * DD;
    k_init<<<(initTot + 255) / 256, 256>>>(n);
    k_wcat<<<(NTILES * KSTEPS * 32 * 2 + 255) / 256, 256>>>(Wb, Wc);
    k_hist<<<(e + 255) / 256, 256>>>(dstp, e);
    k_scanA<<<nb, SCB>>>(n);
    k_scanB<<<1, 32>>>(nb, e, n);
    k_scanC<<<nb, SCB>>>(n);
    k_scatter<<<(e + 255) / 256, 256>>>(srcp, dstp, e);

    dim3 ggrid((n + TBM - 1) / TBM, 2);
    k_gemm_mma<<<ggrid, 256>>>(node, bcomb, n);

    k_gstart<<<1, 128>>>(batchv, n);
    k_agg<<<(n + AGG_WPB - 1) / AGG_WPB, 256>>>(conv_bias, batchv, n);
    k_fin<<<(GG * DD + 255) / 256, 256>>>(gms);
    k_out<<<(n * (DD / 4) + 255) / 256, 256>>>(out, batchv, gw, gb, n);
}

// round 15
// speedup vs baseline: 2.1581x; 1.0303x over previous
#include <cuda_runtime.h>
#include <cuda_fp16.h>
#include <cuda_bf16.h>
#include <cstdint>

// Problem constants (fixed by the dataset)
#define DD   256          // hidden dim
#define BF   128          // B*F bases width
#define HBA  96           // H*B*A comb width
#define NCAT 224          // BF + HBA
#define GG   64           // graphs
#define EPSV 1e-5f

#define MAXN 50176
#define MAXE 851968
#define SCB  1024
#define MAXB ((MAXN + SCB - 1) / SCB)

#define NTILES (NCAT / 8)     // 28 n-tiles of 8 cols
#define KSTEPS (256 / 8)      // 32 k-steps of 8
#define WFRAG_ELEMS (NTILES * KSTEPS * 32 * 2)

// ---------------- device scratch (no allocations allowed) ----------------
__device__ __half g_bases16[MAXN * BF];   // fp16 bases: only consumer is the k_agg gather
__device__ float g_comb [MAXN * HBA];
__device__ float g_h    [(size_t)MAXN * DD];
__device__ float g_Wfrag[WFRAG_ELEMS];    // B in mma-fragment layout, tf32-rounded
__device__ int   g_cnt  [MAXN];
__device__ int   g_off  [MAXN + 1];
__device__ int   g_cur  [MAXN];
__device__ int2  g_edge [MAXE];           // packed {src, bits(dinv[src]*dinv[dst])}
__device__ float g_dinv [MAXN];
__device__ float g_S1   [GG * DD];
__device__ float g_S2   [GG * DD];
__device__ float g_mu   [GG * DD];
__device__ float g_istd [GG * DD];
__device__ int   g_gstart[GG + 1];
__device__ int   g_bsum [MAXB];
__device__ int   g_boff [MAXB];

// ---------------- helpers ----------------
__device__ __forceinline__ float to_tf32(float x) {
    float r;
    asm("cvt.rna.tf32.f32 %0, %1;" : "=f"(r) : "f"(x));
    return r;
}
__device__ __forceinline__ uint32_t tf32_bits(float x) {
    float r;
    asm("cvt.rna.tf32.f32 %0, %1;" : "=f"(r) : "f"(x));
    return __float_as_uint(r);
}
// m16n8k8 tf32 mma (baseline sm_80+ PTX -> HMMA on sm_103, tensor pipe)
__device__ __forceinline__ void mma8(float* c, const uint32_t* a, uint32_t b0, uint32_t b1) {
    asm volatile(
        "mma.sync.aligned.m16n8k8.row.col.f32.tf32.tf32.f32 "
        "{%0,%1,%2,%3}, {%4,%5,%6,%7}, {%8,%9}, {%0,%1,%2,%3};"
        : "+f"(c[0]), "+f"(c[1]), "+f"(c[2]), "+f"(c[3])
        : "r"(a[0]), "r"(a[1]), "r"(a[2]), "r"(a[3]), "r"(b0), "r"(b1));
}
// gather one lane's 4 channels (4 halves = 8B) from a bases row, to f32
__device__ __forceinline__ float4 gather4(int row, int lane) {
    const uint2* p = reinterpret_cast<const uint2*>(g_bases16 + (size_t)row * BF);
    uint2 raw = __ldg(p + lane);
    __half2 h0 = *reinterpret_cast<__half2*>(&raw.x);
    __half2 h1 = *reinterpret_cast<__half2*>(&raw.y);
    float2 f0 = __half22float2(h0);
    float2 f1 = __half22float2(h1);
    return make_float4(f0.x, f0.y, f1.x, f1.y);
}

// ---------------- K0: init counters/stats + build W fragment table ----------------
__global__ void k_init_wcat(int n, const float* __restrict__ Wb, const float* __restrict__ Wc) {
    int i = blockIdx.x * blockDim.x + threadIdx.x;
    if (i < n) g_cnt[i] = 0;
    if (i < GG * DD) { g_S1[i] = 0.f; g_S2[i] = 0.f; }
    if (i < WFRAG_ELEMS) {
        int r    = i & 1;
        int lane = (i >> 1) & 31;
        int ks   = (i >> 6) & 31;
        int nt   = i >> 11;
        int gid = lane >> 2, tig = lane & 3;
        int k = ks * 8 + tig + r * 4;
        int nn = nt * 8 + gid;
        float v = (nn < BF) ? Wb[k * BF + nn] : Wc[k * HBA + (nn - BF)];
        g_Wfrag[i] = to_tf32(v);
    }
}

// ---------------- K2: in-degree histogram over dst ----------------
__global__ void k_hist(const int* __restrict__ dst, int e) {
    int i = blockIdx.x * blockDim.x + threadIdx.x;
    if (i < e) atomicAdd(&g_cnt[dst[i]], 1);
}

// ---------------- K3a: per-block exclusive scan + dinv ----------------
__global__ __launch_bounds__(SCB) void k_scanA(int n) {
    __shared__ int warpsums[32];
    int t = threadIdx.x;
    int lane = t & 31, wrp = t >> 5;
    int i = blockIdx.x * SCB + t;
    int v = (i < n) ? g_cnt[i] : 0;
    int x = v;
    #pragma unroll
    for (int o = 1; o < 32; o <<= 1) {
        int y = __shfl_up_sync(0xFFFFFFFFu, x, o);
        if (lane >= o) x += y;
    }
    if (lane == 31) warpsums[wrp] = x;
    __syncthreads();
    if (t < 32) {
        int s = warpsums[t];
        #pragma unroll
        for (int o = 1; o < 32; o <<= 1) {
            int y = __shfl_up_sync(0xFFFFFFFFu, s, o);
            if (t >= o) s += y;
        }
        warpsums[t] = s;
    }
    __syncthreads();
    int incl = x + ((wrp > 0) ? warpsums[wrp - 1] : 0);
    if (i < n) {
        g_off[i] = incl - v;                    // block-local exclusive
        g_dinv[i] = rsqrtf((float)(v + 1));     // +1 self loop
    }
    if (t == SCB - 1) g_bsum[blockIdx.x] = incl;
}

// ---------------- K3b: 1-warp scan of block sums ----------------
__global__ void k_scanB(int nb, int etot, int n) {
    int lane = threadIdx.x;
    if (lane >= 32) return;
    int carry = 0;
    for (int base = 0; base < nb; base += 32) {
        int idx = base + lane;
        int v = (idx < nb) ? g_bsum[idx] : 0;
        int x = v;
        #pragma unroll
        for (int o = 1; o < 32; o <<= 1) {
            int y = __shfl_up_sync(0xFFFFFFFFu, x, o);
            if (lane >= o) x += y;
        }
        if (idx < nb) g_boff[idx] = carry + x - v;
        carry += __shfl_sync(0xFFFFFFFFu, x, 31);
    }
    if (lane == 0) g_off[n] = etot;
}

// ---------------- K3c: add block offsets ----------------
__global__ __launch_bounds__(SCB) void k_scanC(int n) {
    int i = blockIdx.x * SCB + threadIdx.x;
    if (i >= n) return;
    int e = g_off[i] + g_boff[blockIdx.x];
    g_off[i] = e;
    g_cur[i] = e;
}

// ---------------- K4: scatter packed edge records {src, symweight} ----------------
__global__ void k_scatter(const int* __restrict__ src, const int* __restrict__ dst, int e) {
    int i = blockIdx.x * blockDim.x + threadIdx.x;
    if (i >= e) return;
    int d = dst[i];
    int s = src[i];
    int p = atomicAdd(&g_cur[d], 1);
    float w = g_dinv[s] * g_dinv[d];
    g_edge[p] = make_int2(s, __float_as_int(w));
}

// ---------------- K5: tensor-core TF32 GEMM via mma.sync (fallback HMMA path) ----------------
#define TBM 128
#define TBN 112
__global__ __launch_bounds__(256) void k_gemm_mma(const float* __restrict__ X,
                                                  const float* __restrict__ bcomb, int M) {
    int tid = threadIdx.x;
    int wid = tid >> 5, lane = tid & 31;
    int warp_m = wid & 3;        // 0..3
    int warp_n = wid >> 2;       // 0..1
    int gid = lane >> 2, tig = lane & 3;

    int rowb = blockIdx.x * TBM + warp_m * 32;          // warp's M base
    int coln0 = blockIdx.y * TBN + warp_n * 56;         // warp's N base
    int ntg0 = coln0 >> 3;                              // global n-tile base (7 tiles)

    // clamped row pointers (invalid rows compute garbage, stores are guarded)
    const float* A0 = X + (size_t)min(rowb + gid,      M - 1) * 256;
    const float* A1 = X + (size_t)min(rowb + gid + 8,  M - 1) * 256;
    const float* A2 = X + (size_t)min(rowb + gid + 16, M - 1) * 256;
    const float* A3 = X + (size_t)min(rowb + gid + 24, M - 1) * 256;

    const float2* Bf = reinterpret_cast<const float2*>(g_Wfrag);

    float acc[2][7][4];
    #pragma unroll
    for (int mt = 0; mt < 2; mt++)
        #pragma unroll
        for (int nt = 0; nt < 7; nt++)
            #pragma unroll
            for (int q = 0; q < 4; q++) acc[mt][nt][q] = 0.f;

    #pragma unroll 4
    for (int ks = 0; ks < KSTEPS; ks++) {
        int k0 = ks * 8 + tig;
        uint32_t a0[4], a1[4];
        a0[0] = tf32_bits(__ldg(A0 + k0));
        a0[1] = tf32_bits(__ldg(A1 + k0));
        a0[2] = tf32_bits(__ldg(A0 + k0 + 4));
        a0[3] = tf32_bits(__ldg(A1 + k0 + 4));
        a1[0] = tf32_bits(__ldg(A2 + k0));
        a1[1] = tf32_bits(__ldg(A3 + k0));
        a1[2] = tf32_bits(__ldg(A2 + k0 + 4));
        a1[3] = tf32_bits(__ldg(A3 + k0 + 4));
        #pragma unroll
        for (int nt = 0; nt < 7; nt++) {
            float2 b2 = __ldg(&Bf[((size_t)(ntg0 + nt) * KSTEPS + ks) * 32 + lane]);
            uint32_t b0 = __float_as_uint(b2.x);
            uint32_t b1 = __float_as_uint(b2.y);
            mma8(acc[0][nt], a0, b0, b1);
            mma8(acc[1][nt], a1, b0, b1);
        }
    }

    // epilogue: d0,d1 -> row base+gid, cols col,col+1 ; d2,d3 -> row base+gid+8
    // bases cols -> fp16 (half2 store), comb cols -> f32 + bias
    #pragma unroll
    for (int mt = 0; mt < 2; mt++) {
        int r1 = rowb + mt * 16 + gid;
        int r2 = r1 + 8;
        #pragma unroll
        for (int nt = 0; nt < 7; nt++) {
            int col = coln0 + nt * 8 + tig * 2;
            bool isB = (col < BF);
            float bx = 0.f, by = 0.f;
            if (!isB) { bx = bcomb[col - BF]; by = bcomb[col - BF + 1]; }
            if (r1 < M) {
                if (isB) {
                    __half2 hv = __floats2half2_rn(acc[mt][nt][0], acc[mt][nt][1]);
                    *reinterpret_cast<__half2*>(g_bases16 + (size_t)r1 * BF + col) = hv;
                } else {
                    float2 v = make_float2(acc[mt][nt][0] + bx, acc[mt][nt][1] + by);
                    *(float2*)(g_comb + (size_t)r1 * HBA + (col - BF)) = v;
                }
            }
            if (r2 < M) {
                if (isB) {
                    __half2 hv = __floats2half2_rn(acc[mt][nt][2], acc[mt][nt][3]);
                    *reinterpret_cast<__half2*>(g_bases16 + (size_t)r2 * BF + col) = hv;
                } else {
                    float2 v = make_float2(acc[mt][nt][2] + bx, acc[mt][nt][3] + by);
                    *(float2*)(g_comb + (size_t)r2 * HBA + (col - BF)) = v;
                }
            }
        }
    }
}

// ---------------- K6: graph start offsets (batch is sorted) ----------------
__global__ void k_gstart(const int* __restrict__ batchv, int n) {
    int g = blockIdx.x * blockDim.x + threadIdx.x;
    if (g > GG) return;
    if (g == GG) { g_gstart[GG] = n; return; }
    int lo = 0, hi = n;
    while (lo < hi) {
        int mid = (lo + hi) >> 1;
        if (batchv[mid] < g) lo = mid + 1; else hi = mid;
    }
    g_gstart[g] = lo;
}

// ---------------- K7: warp-per-node aggregate + einsum + stats ----------------
#define AGG_WPB 8
__global__ __launch_bounds__(256) void k_agg(const float* __restrict__ conv_bias,
                                             const int* __restrict__ batchv, int n) {
    __shared__ float sAgg[AGG_WPB][3][128];
    __shared__ float sComb[AGG_WPB][96];
    __shared__ float sH [AGG_WPB][DD];   // per-warp h values for stats reduction
    __shared__ float sH2[AGG_WPB][DD];
    __shared__ int sg0;
    int t = threadIdx.x;
    int w = t >> 5, lane = t & 31;
    int node0 = blockIdx.x * AGG_WPB;
    int node = node0 + w;
    if (t == 0) sg0 = batchv[min(node0, n - 1)];
    __syncthreads();
    int g0 = sg0;

    if (node < n) {
        // prefetch comb early so it overlaps the edge loop
        sComb[w][lane]      = g_comb[(size_t)node * HBA + lane];
        sComb[w][lane + 32] = g_comb[(size_t)node * HBA + lane + 32];
        sComb[w][lane + 64] = g_comb[(size_t)node * HBA + lane + 64];

        const int2* ep = g_edge;
        float di = g_dinv[node];
        float4 bv = gather4(node, lane);
        float w2 = di * di;
        float4 asym = make_float4(bv.x * w2, bv.y * w2, bv.z * w2, bv.w * w2);
        float4 asum = bv;
        float4 amax = bv;
        int beg = g_off[node], end = g_off[node + 1];
        int j = beg;
        // unroll-by-4; fp16 bases payload halves gather traffic
        for (; j + 4 <= end; j += 4) {
            int2 e0 = __ldg(&ep[j]);
            int2 e1 = __ldg(&ep[j + 1]);
            int2 e2 = __ldg(&ep[j + 2]);
            int2 e3 = __ldg(&ep[j + 3]);
            float w0 = __int_as_float(e0.y);
            float w1 = __int_as_float(e1.y);
            float wS2 = __int_as_float(e2.y);
            float w3 = __int_as_float(e3.y);
            float4 m0 = gather4(e0.x, lane);
            float4 m1 = gather4(e1.x, lane);
            float4 m2 = gather4(e2.x, lane);
            float4 m3 = gather4(e3.x, lane);
            asym.x += m0.x * w0 + m1.x * w1 + m2.x * wS2 + m3.x * w3;
            asym.y += m0.y * w0 + m1.y * w1 + m2.y * wS2 + m3.y * w3;
            asym.z += m0.z * w0 + m1.z * w1 + m2.z * wS2 + m3.z * w3;
            asym.w += m0.w * w0 + m1.w * w1 + m2.w * wS2 + m3.w * w3;
            asum.x += m0.x + m1.x + m2.x + m3.x;
            asum.y += m0.y + m1.y + m2.y + m3.y;
            asum.z += m0.z + m1.z + m2.z + m3.z;
            asum.w += m0.w + m1.w + m2.w + m3.w;
            amax.x = fmaxf(fmaxf(fmaxf(amax.x, m0.x), fmaxf(m1.x, m2.x)), m3.x);
            amax.y = fmaxf(fmaxf(fmaxf(amax.y, m0.y), fmaxf(m1.y, m2.y)), m3.y);
            amax.z = fmaxf(fmaxf(fmaxf(amax.z, m0.z), fmaxf(m1.z, m2.z)), m3.z);
            amax.w = fmaxf(fmaxf(fmaxf(amax.w, m0.w), fmaxf(m1.w, m2.w)), m3.w);
        }
        for (; j < end; ++j) {
            int2 e0 = __ldg(&ep[j]);
            float ws = __int_as_float(e0.y);
            float4 m = gather4(e0.x, lane);
            asym.x += m.x * ws; asym.y += m.y * ws; asym.z += m.z * ws; asym.w += m.w * ws;
            asum.x += m.x;      asum.y += m.y;      asum.z += m.z;      asum.w += m.w;
            amax.x = fmaxf(amax.x, m.x); amax.y = fmaxf(amax.y, m.y);
            amax.z = fmaxf(amax.z, m.z); amax.w = fmaxf(amax.w, m.w);
        }
        ((float4*)sAgg[w][0])[lane] = asym;
        ((float4*)sAgg[w][1])[lane] = asum;
        ((float4*)sAgg[w][2])[lane] = amax;
        __syncwarp();
        int g = batchv[node];
        bool local = (g == g0);
        #pragma unroll
        for (int jh = 0; jh < 8; jh++) {  // jh = head
            int tt = jh * 32 + lane;      // output channel
            float acc = conv_bias[tt];
            #pragma unroll
            for (int k = 0; k < 12; k++)  // k = a*B + b
                acc += sComb[w][jh * 12 + k] * sAgg[w][k >> 2][(k & 3) * 32 + lane];
            g_h[(size_t)node * DD + tt] = acc;
            float a2 = acc * acc;
            if (local) {
                sH[w][tt] = acc;
                sH2[w][tt] = a2;
            } else {
                sH[w][tt] = 0.f;
                sH2[w][tt] = 0.f;
                atomicAdd(&g_S1[g * DD + tt], acc);
                atomicAdd(&g_S2[g * DD + tt], a2);
            }
        }
    } else {
        // inactive warp: zero its reduction rows
        #pragma unroll
        for (int jh = 0; jh < 8; jh++) {
            int tt = jh * 32 + lane;
            sH[w][tt] = 0.f;
            sH2[w][tt] = 0.f;
        }
    }
    __syncthreads();
    if (t < DD) {
        float s1 = 0.f, s2 = 0.f;
        #pragma unroll
        for (int ww = 0; ww < AGG_WPB; ww++) { s1 += sH[ww][t]; s2 += sH2[ww][t]; }
        atomicAdd(&g_S1[g0 * DD + t], s1);
        atomicAdd(&g_S2[g0 * DD + t], s2);
    }
}

// ---------------- K8: finalize GraphNorm statistics ----------------
__global__ void k_fin(const float* __restrict__ alpha_v) {
    int i = blockIdx.x * blockDim.x + threadIdx.x;
    if (i >= GG * DD) return;
    int g = i / DD, d = i % DD;
    int cs = g_gstart[g + 1] - g_gstart[g];
    float c = fmaxf((float)cs, 1.f);
    float m = g_S1[i] / c;
    float a = alpha_v[d];
    float var = g_S2[i] / c - (2.f * a - a * a) * m * m;
    g_mu[i] = a * m;
    g_istd[i] = rsqrtf(var + EPSV);
}

// ---------------- K9: normalize + relu ----------------
__global__ void k_out(float* __restrict__ out, const int* __restrict__ batchv,
                      const float* __restrict__ gamma, const float* __restrict__ beta, int n) {
    int idx = blockIdx.x * blockDim.x + threadIdx.x;
    int total = n * (DD / 4);
    if (idx >= total) return;
    int node = idx >> 6;          // DD/4 = 64 float4 per row
    int c4 = idx & 63;
    int g = __ldg(&batchv[node]);
    float4 hv = ((const float4*)g_h)[idx];
    int d = c4 * 4;
    float4 mu = *(const float4*)(g_mu + g * DD + d);
    float4 is = *(const float4*)(g_istd + g * DD + d);
    float4 ga = *(const float4*)(gamma + d);
    float4 be = *(const float4*)(beta + d);
    float4 r;
    r.x = fmaxf(0.f, ga.x * (hv.x - mu.x) * is.x + be.x);
    r.y = fmaxf(0.f, ga.y * (hv.y - mu.y) * is.y + be.y);
    r.z = fmaxf(0.f, ga.z * (hv.z - mu.z) * is.z + be.z);
    r.w = fmaxf(0.f, ga.w * (hv.w - mu.w) * is.w + be.w);
    ((float4*)out)[idx] = r;
}

// ---------------- launcher ----------------
extern "C" void kernel_launch(void* const* d_in, const int* in_sizes, int n_in,
                              void* d_out, int out_size) {
    const float* node      = (const float*)d_in[0];
    const float* Wb        = (const float*)d_in[2];
    const float* Wc        = (const float*)d_in[3];
    const float* bcomb     = (const float*)d_in[4];
    const float* conv_bias = (const float*)d_in[5];
    const float* gw        = (const float*)d_in[6];
    const float* gb        = (const float*)d_in[7];
    const float* gms       = (const float*)d_in[8];
    const int*   ei        = (const int*)d_in[9];
    const int*   batchv    = (const int*)d_in[10];
    int n = in_sizes[10];
    int e = in_sizes[9] / 2;
    const int* srcp = ei;
    const int* dstp = ei + e;
    float* out = (float*)d_out;

    int nb = (n + SCB - 1) / SCB;
    int initTot = n;
    if (WFRAG_ELEMS > initTot) initTot = WFRAG_ELEMS;
    if (GG * DD > initTot) initTot = GG * DD;
    k_init_wcat<<<(initTot + 255) / 256, 256>>>(n, Wb, Wc);
    k_hist<<<(e + 255) / 256, 256>>>(dstp, e);
    k_scanA<<<nb, SCB>>>(n);
    k_scanB<<<1, 32>>>(nb, e, n);
    k_scanC<<<nb, SCB>>>(n);
    k_scatter<<<(e + 255) / 256, 256>>>(srcp, dstp, e);

    dim3 ggrid((n + TBM - 1) / TBM, 2);
    k_gemm_mma<<<ggrid, 256>>>(node, bcomb, n);

    k_gstart<<<1, 128>>>(batchv, n);
    k_agg<<<(n + AGG_WPB - 1) / AGG_WPB, 256>>>(conv_bias, batchv, n);
    k_fin<<<(GG * DD + 255) / 256, 256>>>(gms);
    k_out<<<(n * (DD / 4) + 255) / 256, 256>>>(out, batchv, gw, gb, n);
}